// round 11
// baseline (speedup 1.0000x reference)
#include <cuda_runtime.h>
#include <cuda_fp16.h>
#include <math.h>
#include <stdint.h>

#define N_NODES 50000
#define N_EDGES 800000
#define N_GRAPHS 512
#define IN_DIM 126
#define DIMH 128
#define LIN1_DIM 64
#define BN_EPS 1e-5f

#define SCAN_NB 49   // ceil(50000/1024)
#define KPAIRS 64    // 128 k / 2 per u32

// ---------------- device scratch ----------------
__device__ uint32_t g_fh[N_NODES * KPAIRS];    // features, packed fp16 (half2)
__device__ uint32_t g_ah[N_NODES * KPAIRS];    // agg output hi plane
__device__ uint32_t g_al[N_NODES * KPAIRS];    // agg output lo (residual) plane
__device__ uint32_t g_wsp[6 * KPAIRS * 128];   // pre-split fp16 weights, slot-major
__device__ int      g_cnt[N_NODES];
__device__ int      g_off[N_NODES + 1];
__device__ int      g_cur[N_NODES];
__device__ int      g_srcs[N_EDGES];
__device__ float    g_pool[N_GRAPHS * DIMH];
__device__ int      g_bsum[64];
__device__ int      g_bofs[64];
__device__ int      g_gstart[N_GRAPHS + 1];

// ---------------- CSR build ----------------
__global__ void count_kernel(const int* __restrict__ dst) {
    int i = blockIdx.x * blockDim.x + threadIdx.x;
    if (i < N_EDGES) atomicAdd(&g_cnt[dst[i]], 1);
}

__global__ void block_sum_kernel() {
    __shared__ int ws[32];
    int i = blockIdx.x * 1024 + threadIdx.x;
    int lane = threadIdx.x & 31, wid = threadIdx.x >> 5;
    int v = (i < N_NODES) ? g_cnt[i] : 0;
    #pragma unroll
    for (int o = 16; o > 0; o >>= 1) v += __shfl_down_sync(0xFFFFFFFFu, v, o);
    if (lane == 0) ws[wid] = v;
    __syncthreads();
    if (wid == 0) {
        int s = ws[lane];
        #pragma unroll
        for (int o = 16; o > 0; o >>= 1) s += __shfl_down_sync(0xFFFFFFFFu, s, o);
        if (lane == 0) g_bsum[blockIdx.x] = s;
    }
}

__global__ void scan_sums_kernel() {
    __shared__ int sh[64];
    int t = threadIdx.x;
    int v = (t < SCAN_NB) ? g_bsum[t] : 0;
    sh[t] = v;
    __syncthreads();
    #pragma unroll
    for (int o = 1; o < 64; o <<= 1) {
        int u = (t >= o) ? sh[t - o] : 0;
        __syncthreads();
        sh[t] += u;
        __syncthreads();
    }
    if (t < SCAN_NB) g_bofs[t] = sh[t] - v;
    if (t == 63) g_off[N_NODES] = sh[63];
}

__global__ void block_scan_kernel() {
    __shared__ int ws[32];
    int i = blockIdx.x * 1024 + threadIdx.x;
    int lane = threadIdx.x & 31, wid = threadIdx.x >> 5;
    int v = (i < N_NODES) ? g_cnt[i] : 0;
    int x = v;
    #pragma unroll
    for (int o = 1; o < 32; o <<= 1) {
        int t = __shfl_up_sync(0xFFFFFFFFu, x, o);
        if (lane >= o) x += t;
    }
    if (lane == 31) ws[wid] = x;
    __syncthreads();
    if (wid == 0) {
        int s = ws[lane];
        #pragma unroll
        for (int o = 1; o < 32; o <<= 1) {
            int t = __shfl_up_sync(0xFFFFFFFFu, s, o);
            if (lane >= o) s += t;
        }
        ws[lane] = s;
    }
    __syncthreads();
    if (i < N_NODES) {
        int excl = g_bofs[blockIdx.x] + x - v + (wid > 0 ? ws[wid - 1] : 0);
        g_off[i] = excl;
        g_cur[i] = excl;
    }
}

__global__ void scatter_kernel(const int* __restrict__ src, const int* __restrict__ dst) {
    int i = blockIdx.x * blockDim.x + threadIdx.x;
    if (i < N_EDGES) {
        int p = atomicAdd(&g_cur[dst[i]], 1);
        g_srcs[p] = src[i];
    }
}

// pad x [N,126] fp32 -> g_fh [N,64] packed fp16
__global__ void pad_x_kernel(const float* __restrict__ x) {
    int i = blockIdx.x * blockDim.x + threadIdx.x;
    if (i < N_NODES * 64) {
        int n = i >> 6, p = i & 63;
        float2 v = make_float2(0.f, 0.f);
        if (p < 63) v = *(const float2*)&x[n * IN_DIM + 2 * p];
        __half2 h = __floats2half2_rn(v.x, v.y);
        g_fh[i] = *(uint32_t*)&h;
    }
}

__global__ void gstart_kernel(const int* __restrict__ batch) {
    int i = blockIdx.x * blockDim.x + threadIdx.x;
    if (i >= N_NODES) return;
    int b = batch[i];
    int bp = (i == 0) ? -1 : batch[i - 1];
    for (int gg = bp + 1; gg <= b; gg++) g_gstart[gg] = i;
    if (i == N_NODES - 1)
        for (int gg = b + 1; gg <= N_GRAPHS; gg++) g_gstart[gg] = N_NODES;
}

// ---------------- weight pre-split: fp32 [K,128] -> packed half2 ------------
__global__ void wsplit_kernel(const float* __restrict__ w1a, const float* __restrict__ w2a,
                              const float* __restrict__ w1b, const float* __restrict__ w2b,
                              const float* __restrict__ w1c, const float* __restrict__ w2c,
                              int Kw1) {
    int slot = blockIdx.y;
    const float* w = (slot == 0) ? w1a : (slot == 1) ? w2a : (slot == 2) ? w1b
                   : (slot == 3) ? w2b : (slot == 4) ? w1c : w2c;
    int Kw = (slot == 0) ? Kw1 : DIMH;
    int i = blockIdx.x * blockDim.x + threadIdx.x;
    if (i >= KPAIRS * 128) return;
    int kp = i >> 7, n = i & 127;
    int k0 = 2 * kp, k1 = k0 + 1;
    float v0 = (k0 < Kw) ? w[k0 * DIMH + n] : 0.0f;
    float v1 = (k1 < Kw) ? w[k1 * DIMH + n] : 0.0f;
    __half2 h = __floats2half2_rn(v0, v1);
    g_wsp[slot * KPAIRS * 128 + i] = *(uint32_t*)&h;
}

// ---------------- aggregation: 16 lanes/node (2 nodes/warp), uint4 rows -----
// lane owns 8 features (uint4 = 4 half2). fp32 accumulate, emit hi/lo planes.
__global__ __launch_bounds__(256) void agg_kernel(const uint32_t* __restrict__ F,
                                                  uint32_t* __restrict__ oh,
                                                  uint32_t* __restrict__ ol) {
    int gtid = blockIdx.x * blockDim.x + threadIdx.x;
    int node = gtid >> 4;                 // 16 threads per node
    if (node >= N_NODES) return;
    int hl   = gtid & 15;                 // lane within half-warp
    int lane = threadIdx.x & 31;
    int hsel = lane & 16;                 // 0 or 16: which half-warp

    int s = g_off[node], e = g_off[node + 1];

    float acc[8];
    {
        uint4 v = *(const uint4*)&F[node * KPAIRS + hl * 4];
        float2 f0 = __half22float2(*(__half2*)&v.x);
        float2 f1 = __half22float2(*(__half2*)&v.y);
        float2 f2 = __half22float2(*(__half2*)&v.z);
        float2 f3 = __half22float2(*(__half2*)&v.w);
        acc[0] = f0.x; acc[1] = f0.y; acc[2] = f1.x; acc[3] = f1.y;
        acc[4] = f2.x; acc[5] = f2.y; acc[6] = f3.x; acc[7] = f3.y;
    }

    for (int base = s; base < e; base += 16) {
        int cnt = min(16, e - base);
        int idx = (base + hl < e) ? g_srcs[base + hl] : 0;
        int j = 0;
        for (; j + 4 <= cnt; j += 4) {
            int s0 = __shfl_sync(0xFFFFFFFFu, idx, hsel | (j    ));
            int s1 = __shfl_sync(0xFFFFFFFFu, idx, hsel | (j + 1));
            int s2 = __shfl_sync(0xFFFFFFFFu, idx, hsel | (j + 2));
            int s3 = __shfl_sync(0xFFFFFFFFu, idx, hsel | (j + 3));
            uint4 v0 = *(const uint4*)&F[s0 * KPAIRS + hl * 4];
            uint4 v1 = *(const uint4*)&F[s1 * KPAIRS + hl * 4];
            uint4 v2 = *(const uint4*)&F[s2 * KPAIRS + hl * 4];
            uint4 v3 = *(const uint4*)&F[s3 * KPAIRS + hl * 4];
            #pragma unroll
            for (int q = 0; q < 4; q++) {
                uint32_t u0 = (&v0.x)[q], u1 = (&v1.x)[q];
                uint32_t u2 = (&v2.x)[q], u3 = (&v3.x)[q];
                float2 f0 = __half22float2(*(__half2*)&u0);
                float2 f1 = __half22float2(*(__half2*)&u1);
                float2 f2 = __half22float2(*(__half2*)&u2);
                float2 f3 = __half22float2(*(__half2*)&u3);
                acc[2 * q]     += (f0.x + f1.x) + (f2.x + f3.x);
                acc[2 * q + 1] += (f0.y + f1.y) + (f2.y + f3.y);
            }
        }
        for (; j < cnt; j++) {
            int s0 = __shfl_sync(0xFFFFFFFFu, idx, hsel | j);
            uint4 v = *(const uint4*)&F[s0 * KPAIRS + hl * 4];
            #pragma unroll
            for (int q = 0; q < 4; q++) {
                uint32_t u = (&v.x)[q];
                float2 f = __half22float2(*(__half2*)&u);
                acc[2 * q]     += f.x;
                acc[2 * q + 1] += f.y;
            }
        }
    }

    // split fp32 acc into fp16 hi + fp16 residual; store uint4 per plane
    uint4 hv, lv;
    #pragma unroll
    for (int q = 0; q < 4; q++) {
        __half h0 = __float2half_rn(acc[2 * q]);
        __half h1 = __float2half_rn(acc[2 * q + 1]);
        __half2 hp = __halves2half2(h0, h1);
        __half2 lp = __floats2half2_rn(acc[2 * q]     - __half2float(h0),
                                       acc[2 * q + 1] - __half2float(h1));
        (&hv.x)[q] = *(uint32_t*)&hp;
        (&lv.x)[q] = *(uint32_t*)&lp;
    }
    *(uint4*)&oh[node * KPAIRS + hl * 4] = hv;
    *(uint4*)&ol[node * KPAIRS + hl * 4] = lv;
}

// ---------------- fp16 helpers ----------------
__device__ __forceinline__ uint32_t pack_f16x2(__half a, __half b) {
    __half2 p = __halves2half2(a, b);
    return *(uint32_t*)&p;
}
__device__ __forceinline__ void mma_f16(float* c, const uint32_t* a, const uint32_t* b) {
    asm volatile(
        "mma.sync.aligned.m16n8k16.row.col.f32.f16.f16.f32 "
        "{%0,%1,%2,%3}, {%4,%5,%6,%7}, {%8,%9}, {%0,%1,%2,%3};\n"
        : "+f"(c[0]), "+f"(c[1]), "+f"(c[2]), "+f"(c[3])
        : "r"(a[0]), "r"(a[1]), "r"(a[2]), "r"(a[3]), "r"(b[0]), "r"(b[1]));
}

// ---------------- fused double-GEMM per GIN layer, 64-row tile, fp16 --------
#define AST 20
#define BST 136
#define HST 68
#define SM_AH 0
#define SM_AL (64 * AST)
#define SM_B  (2 * 64 * AST)
#define SM_HH (SM_B + 16 * BST)
#define SM_HL (SM_HH + 64 * HST)
#define SMEM_U32 (SM_HH + 2 * 64 * HST)

__global__ __launch_bounds__(256, 3) void layer_gemm_kernel(
    const uint32_t* __restrict__ Ahg, const uint32_t* __restrict__ Alg,
    const uint32_t* __restrict__ W1p, const float* __restrict__ b1,
    const float* __restrict__ gamma, const float* __restrict__ beta,
    const float* __restrict__ mean, const float* __restrict__ var,
    const uint32_t* __restrict__ W2p, const float* __restrict__ b2,
    uint32_t* __restrict__ OUT16)
{
    extern __shared__ uint32_t sm[];
    uint32_t* Ah = sm + SM_AH;
    uint32_t* Al = sm + SM_AL;
    uint32_t* B  = sm + SM_B;
    uint32_t* Hh = sm + SM_HH;
    uint32_t* Hl = sm + SM_HL;

    const int tid  = threadIdx.x;
    const int wid  = tid >> 5;
    const int lane = tid & 31;
    const int g    = lane >> 2;
    const int tig  = lane & 3;
    const int wm   = wid & 1;
    const int wn   = wid >> 1;
    const int row0 = blockIdx.x * 64;

    float acc[2][4][4];

    // =========== GEMM1 ===========
    #pragma unroll
    for (int mi = 0; mi < 2; mi++)
        #pragma unroll
        for (int ni = 0; ni < 4; ni++)
            #pragma unroll
            for (int r = 0; r < 4; r++) acc[mi][ni][r] = 0.0f;

    for (int c = 0; c < 4; c++) {
        {
            int r = tid >> 2, kp4 = (tid & 3) * 4;
            int gr = row0 + r;
            uint4 vh = make_uint4(0, 0, 0, 0), vl = make_uint4(0, 0, 0, 0);
            if (gr < N_NODES) {
                vh = *(const uint4*)&Ahg[gr * KPAIRS + c * 16 + kp4];
                vl = *(const uint4*)&Alg[gr * KPAIRS + c * 16 + kp4];
            }
            *(uint4*)&Ah[r * AST + kp4] = vh;
            *(uint4*)&Al[r * AST + kp4] = vl;
        }
        #pragma unroll
        for (int l = 0; l < 2; l++) {
            int idx = tid + l * 256;
            int kp = idx >> 5;
            int c4 = (idx & 31) * 4;
            uint4 v = *(const uint4*)&W1p[(c * 16 + kp) * 128 + c4];
            *(uint4*)&B[kp * BST + c4] = v;
        }
        __syncthreads();

        #pragma unroll
        for (int ks = 0; ks < 2; ks++) {
            const int kk2 = ks * 8;
            uint32_t a_hi[2][4], a_lo[2][4];
            #pragma unroll
            for (int mi = 0; mi < 2; mi++) {
                int rm = wm * 32 + mi * 16;
                a_hi[mi][0] = Ah[(rm + g    ) * AST + kk2 + tig    ];
                a_hi[mi][1] = Ah[(rm + g + 8) * AST + kk2 + tig    ];
                a_hi[mi][2] = Ah[(rm + g    ) * AST + kk2 + tig + 4];
                a_hi[mi][3] = Ah[(rm + g + 8) * AST + kk2 + tig + 4];
                a_lo[mi][0] = Al[(rm + g    ) * AST + kk2 + tig    ];
                a_lo[mi][1] = Al[(rm + g + 8) * AST + kk2 + tig    ];
                a_lo[mi][2] = Al[(rm + g    ) * AST + kk2 + tig + 4];
                a_lo[mi][3] = Al[(rm + g + 8) * AST + kk2 + tig + 4];
            }
            #pragma unroll
            for (int ni = 0; ni < 4; ni++) {
                int cn = wn * 32 + ni * 8;
                uint32_t b[2];
                b[0] = B[(kk2 + tig    ) * BST + cn + g];
                b[1] = B[(kk2 + tig + 4) * BST + cn + g];
                #pragma unroll
                for (int mi = 0; mi < 2; mi++) {
                    mma_f16(acc[mi][ni], a_hi[mi], b);
                    mma_f16(acc[mi][ni], a_lo[mi], b);
                }
            }
        }
        __syncthreads();
    }

    // ---- epilogue1: BN+ReLU, split hi/lo -> Hh/Hl ----
    {
        float sc[4][2], sh[4][2];
        #pragma unroll
        for (int ni = 0; ni < 4; ni++) {
            #pragma unroll
            for (int j = 0; j < 2; j++) {
                int col = wn * 32 + ni * 8 + 2 * tig + j;
                float s = gamma[col] * rsqrtf(var[col] + BN_EPS);
                sc[ni][j] = s;
                sh[ni][j] = beta[col] - mean[col] * s + b1[col] * s;
            }
        }
        #pragma unroll
        for (int mi = 0; mi < 2; mi++) {
            int r0 = wm * 32 + mi * 16 + g;
            int r1 = r0 + 8;
            #pragma unroll
            for (int ni = 0; ni < 4; ni++) {
                int kp = wn * 16 + ni * 4 + tig;
                float o00 = fmaxf(acc[mi][ni][0] * sc[ni][0] + sh[ni][0], 0.0f);
                float o01 = fmaxf(acc[mi][ni][1] * sc[ni][1] + sh[ni][1], 0.0f);
                float o10 = fmaxf(acc[mi][ni][2] * sc[ni][0] + sh[ni][0], 0.0f);
                float o11 = fmaxf(acc[mi][ni][3] * sc[ni][1] + sh[ni][1], 0.0f);
                __half h00 = __float2half_rn(o00), h01 = __float2half_rn(o01);
                __half h10 = __float2half_rn(o10), h11 = __float2half_rn(o11);
                __half2 l0 = __floats2half2_rn(o00 - __half2float(h00),
                                               o01 - __half2float(h01));
                __half2 l1 = __floats2half2_rn(o10 - __half2float(h10),
                                               o11 - __half2float(h11));
                Hh[r0 * HST + kp] = pack_f16x2(h00, h01);
                Hl[r0 * HST + kp] = *(uint32_t*)&l0;
                Hh[r1 * HST + kp] = pack_f16x2(h10, h11);
                Hl[r1 * HST + kp] = *(uint32_t*)&l1;
            }
        }
    }

    // =========== GEMM2 ===========
    #pragma unroll
    for (int mi = 0; mi < 2; mi++)
        #pragma unroll
        for (int ni = 0; ni < 4; ni++)
            #pragma unroll
            for (int r = 0; r < 4; r++) acc[mi][ni][r] = 0.0f;

    for (int c = 0; c < 4; c++) {
        __syncthreads();
        #pragma unroll
        for (int l = 0; l < 2; l++) {
            int idx = tid + l * 256;
            int kp = idx >> 5;
            int c4 = (idx & 31) * 4;
            uint4 v = *(const uint4*)&W2p[(c * 16 + kp) * 128 + c4];
            *(uint4*)&B[kp * BST + c4] = v;
        }
        __syncthreads();

        #pragma unroll
        for (int ks = 0; ks < 2; ks++) {
            const int kp0 = c * 16 + ks * 8;
            uint32_t a_hi[2][4], a_lo[2][4];
            #pragma unroll
            for (int mi = 0; mi < 2; mi++) {
                int rm = wm * 32 + mi * 16;
                a_hi[mi][0] = Hh[(rm + g    ) * HST + kp0 + tig    ];
                a_hi[mi][1] = Hh[(rm + g + 8) * HST + kp0 + tig    ];
                a_hi[mi][2] = Hh[(rm + g    ) * HST + kp0 + tig + 4];
                a_hi[mi][3] = Hh[(rm + g + 8) * HST + kp0 + tig + 4];
                a_lo[mi][0] = Hl[(rm + g    ) * HST + kp0 + tig    ];
                a_lo[mi][1] = Hl[(rm + g + 8) * HST + kp0 + tig    ];
                a_lo[mi][2] = Hl[(rm + g    ) * HST + kp0 + tig + 4];
                a_lo[mi][3] = Hl[(rm + g + 8) * HST + kp0 + tig + 4];
            }
            const int kb = ks * 8;
            #pragma unroll
            for (int ni = 0; ni < 4; ni++) {
                int cn = wn * 32 + ni * 8;
                uint32_t b[2];
                b[0] = B[(kb + tig    ) * BST + cn + g];
                b[1] = B[(kb + tig + 4) * BST + cn + g];
                #pragma unroll
                for (int mi = 0; mi < 2; mi++) {
                    mma_f16(acc[mi][ni], a_hi[mi], b);
                    mma_f16(acc[mi][ni], a_lo[mi], b);
                }
            }
        }
    }

    // ---- epilogue2: bias + ReLU -> packed fp16 OUT ----
    float bb[4][2];
    #pragma unroll
    for (int ni = 0; ni < 4; ni++) {
        #pragma unroll
        for (int j = 0; j < 2; j++)
            bb[ni][j] = b2[wn * 32 + ni * 8 + 2 * tig + j];
    }
    #pragma unroll
    for (int mi = 0; mi < 2; mi++) {
        int r0 = row0 + wm * 32 + mi * 16 + g;
        int r1 = r0 + 8;
        #pragma unroll
        for (int ni = 0; ni < 4; ni++) {
            int c0 = wn * 32 + ni * 8 + 2 * tig;   // even
            int kp = c0 >> 1;
            if (r0 < N_NODES) {
                __half2 o = __floats2half2_rn(
                    fmaxf(acc[mi][ni][0] + bb[ni][0], 0.0f),
                    fmaxf(acc[mi][ni][1] + bb[ni][1], 0.0f));
                OUT16[r0 * KPAIRS + kp] = *(uint32_t*)&o;
            }
            if (r1 < N_NODES) {
                __half2 o = __floats2half2_rn(
                    fmaxf(acc[mi][ni][2] + bb[ni][0], 0.0f),
                    fmaxf(acc[mi][ni][3] + bb[ni][1], 0.0f));
                OUT16[r1 * KPAIRS + kp] = *(uint32_t*)&o;
            }
        }
    }
}

// ---------------- segment pooling over fp16 features ------------------------
__global__ void pool_seg_kernel(const uint32_t* __restrict__ h, float* __restrict__ pool) {
    int gph = blockIdx.x;
    int t = threadIdx.x;       // 0..127 -> feature t
    int u = t >> 1, hi = t & 1;
    int s = g_gstart[gph], e = g_gstart[gph + 1];
    float a0 = 0.f, a1 = 0.f;
    int r = s;
    for (; r + 2 <= e; r += 2) {
        uint32_t v0 = h[r * KPAIRS + u];
        uint32_t v1 = h[(r + 1) * KPAIRS + u];
        float2 f0 = __half22float2(*(__half2*)&v0);
        float2 f1 = __half22float2(*(__half2*)&v1);
        a0 += hi ? f0.y : f0.x;
        a1 += hi ? f1.y : f1.x;
    }
    if (r < e) {
        uint32_t v = h[r * KPAIRS + u];
        float2 f = __half22float2(*(__half2*)&v);
        a0 += hi ? f.y : f.x;
    }
    pool[gph * DIMH + t] = a0 + a1;
}

// ---------------- head ----------------
__global__ void head_kernel(const float* __restrict__ pool,
                            const float* __restrict__ l1w, const float* __restrict__ l1b,
                            const float* __restrict__ l2w, const float* __restrict__ l2b,
                            float* __restrict__ out) {
    __shared__ float hg[DIMH];
    __shared__ float o1[LIN1_DIM];
    int gph = blockIdx.x;
    int t = threadIdx.x;  // 128
    hg[t] = pool[gph * DIMH + t];
    __syncthreads();
    if (t < LIN1_DIM) {
        float s = l1b[t];
        #pragma unroll 8
        for (int k = 0; k < DIMH; k++) s += hg[k] * l1w[k * LIN1_DIM + t];
        o1[t] = fmaxf(s, 0.0f);
    }
    __syncthreads();
    if (t == 0) {
        float s = l2b[0];
        #pragma unroll 8
        for (int j = 0; j < LIN1_DIM; j++) s += o1[j] * l2w[j];
        out[gph] = 1.0f / (1.0f + expf(-s));
    }
}

// ---------------- launch ----------------
extern "C" void kernel_launch(void* const* d_in, const int* in_sizes, int n_in,
                              void* d_out, int out_size) {
    const float* x          = (const float*)d_in[0];
    const int*   edge_index = (const int*)d_in[1];
    const int*   batch      = (const int*)d_in[2];
    const float* w[3][7];
    const float* b2[3];
    for (int l = 0; l < 3; l++) {
        int base = 3 + l * 8;
        w[l][0] = (const float*)d_in[base + 0];
        w[l][1] = (const float*)d_in[base + 1];
        w[l][2] = (const float*)d_in[base + 2];
        w[l][3] = (const float*)d_in[base + 3];
        w[l][4] = (const float*)d_in[base + 4];
        w[l][5] = (const float*)d_in[base + 5];
        w[l][6] = (const float*)d_in[base + 6];
        b2[l]   = (const float*)d_in[base + 7];
    }
    const float* l1w = (const float*)d_in[27];
    const float* l1b = (const float*)d_in[28];
    const float* l2w = (const float*)d_in[29];
    const float* l2b = (const float*)d_in[30];
    float* out = (float*)d_out;

    const int* e_src = edge_index;
    const int* e_dst = edge_index + N_EDGES;

    static uint32_t* p_fh   = nullptr;
    static uint32_t* p_ah   = nullptr;
    static uint32_t* p_al   = nullptr;
    static uint32_t* p_wsp  = nullptr;
    static int*      p_cnt  = nullptr;
    static float*    p_pool = nullptr;
    if (!p_fh) {
        cudaGetSymbolAddress((void**)&p_fh,   g_fh);
        cudaGetSymbolAddress((void**)&p_ah,   g_ah);
        cudaGetSymbolAddress((void**)&p_al,   g_al);
        cudaGetSymbolAddress((void**)&p_wsp,  g_wsp);
        cudaGetSymbolAddress((void**)&p_cnt,  g_cnt);
        cudaGetSymbolAddress((void**)&p_pool, g_pool);
        cudaFuncSetAttribute(layer_gemm_kernel,
                             cudaFuncAttributeMaxDynamicSharedMemorySize,
                             SMEM_U32 * 4);
    }

    // ---- CSR build ----
    cudaMemsetAsync(p_cnt, 0, N_NODES * sizeof(int));
    count_kernel<<<(N_EDGES + 255) / 256, 256>>>(e_dst);
    block_sum_kernel<<<SCAN_NB, 1024>>>();
    scan_sums_kernel<<<1, 64>>>();
    block_scan_kernel<<<SCAN_NB, 1024>>>();
    scatter_kernel<<<(N_EDGES + 255) / 256, 256>>>(e_src, e_dst);

    // ---- pad x, graph boundaries, weight pre-split ----
    pad_x_kernel<<<(N_NODES * 64 + 255) / 256, 256>>>(x);
    gstart_kernel<<<(N_NODES + 255) / 256, 256>>>(batch);
    {
        dim3 grid((KPAIRS * 128 + 255) / 256, 6);
        wsplit_kernel<<<grid, 256>>>(w[0][0], w[0][6], w[1][0], w[1][6],
                                     w[2][0], w[2][6], IN_DIM);
    }

    const int GEMM_GRID = (N_NODES + 63) / 64;
    const int AGG_GRID  = (N_NODES * 16 + 255) / 256;
    const size_t SMEM   = SMEM_U32 * 4;

    // ---- 3 GIN layers ----
    for (int l = 0; l < 3; l++) {
        agg_kernel<<<AGG_GRID, 256>>>(p_fh, p_ah, p_al);
        layer_gemm_kernel<<<GEMM_GRID, 256, SMEM>>>(
            p_ah, p_al,
            p_wsp + (2 * l) * KPAIRS * 128, w[l][1], w[l][2], w[l][3],
            w[l][4], w[l][5],
            p_wsp + (2 * l + 1) * KPAIRS * 128, b2[l],
            p_fh);
    }

    // ---- pool + head ----
    pool_seg_kernel<<<N_GRAPHS, 128>>>(p_fh, p_pool);
    head_kernel<<<N_GRAPHS, 128>>>(p_pool, l1w, l1b, l2w, l2b, out);
}

// round 12
// speedup vs baseline: 1.0612x; 1.0612x over previous
#include <cuda_runtime.h>
#include <cuda_fp16.h>
#include <math.h>
#include <stdint.h>

#define N_NODES 50000
#define N_EDGES 800000
#define N_GRAPHS 512
#define IN_DIM 126
#define DIMH 128
#define LIN1_DIM 64
#define BN_EPS 1e-5f

#define SCAN_NB 49   // ceil(50000/1024)
#define KPAIRS 64    // 128 k / 2 per u32

// ---------------- device scratch ----------------
__device__ uint32_t g_fh[N_NODES * KPAIRS];    // features, packed fp16 (half2)
__device__ uint32_t g_ah[N_NODES * KPAIRS];    // agg output hi plane
__device__ uint32_t g_al[N_NODES * KPAIRS];    // agg output lo (residual) plane
__device__ uint32_t g_wsp[6 * KPAIRS * 128];   // pre-split fp16 weights, slot-major
__device__ int      g_cnt[N_NODES];
__device__ int      g_off[N_NODES + 1];
__device__ int      g_cur[N_NODES];
__device__ int      g_srcs[N_EDGES];
__device__ float    g_pool[N_GRAPHS * DIMH];
__device__ int      g_bsum[64];
__device__ int      g_bofs[64];
__device__ int      g_gstart[N_GRAPHS + 1];

// ---------------- CSR build ----------------
__global__ void count_kernel(const int* __restrict__ dst) {
    int i = blockIdx.x * blockDim.x + threadIdx.x;
    if (i < N_EDGES) atomicAdd(&g_cnt[dst[i]], 1);
}

__global__ void block_sum_kernel() {
    __shared__ int ws[32];
    int i = blockIdx.x * 1024 + threadIdx.x;
    int lane = threadIdx.x & 31, wid = threadIdx.x >> 5;
    int v = (i < N_NODES) ? g_cnt[i] : 0;
    #pragma unroll
    for (int o = 16; o > 0; o >>= 1) v += __shfl_down_sync(0xFFFFFFFFu, v, o);
    if (lane == 0) ws[wid] = v;
    __syncthreads();
    if (wid == 0) {
        int s = ws[lane];
        #pragma unroll
        for (int o = 16; o > 0; o >>= 1) s += __shfl_down_sync(0xFFFFFFFFu, s, o);
        if (lane == 0) g_bsum[blockIdx.x] = s;
    }
}

__global__ void scan_sums_kernel() {
    __shared__ int sh[64];
    int t = threadIdx.x;
    int v = (t < SCAN_NB) ? g_bsum[t] : 0;
    sh[t] = v;
    __syncthreads();
    #pragma unroll
    for (int o = 1; o < 64; o <<= 1) {
        int u = (t >= o) ? sh[t - o] : 0;
        __syncthreads();
        sh[t] += u;
        __syncthreads();
    }
    if (t < SCAN_NB) g_bofs[t] = sh[t] - v;
    if (t == 63) g_off[N_NODES] = sh[63];
}

__global__ void block_scan_kernel() {
    __shared__ int ws[32];
    int i = blockIdx.x * 1024 + threadIdx.x;
    int lane = threadIdx.x & 31, wid = threadIdx.x >> 5;
    int v = (i < N_NODES) ? g_cnt[i] : 0;
    int x = v;
    #pragma unroll
    for (int o = 1; o < 32; o <<= 1) {
        int t = __shfl_up_sync(0xFFFFFFFFu, x, o);
        if (lane >= o) x += t;
    }
    if (lane == 31) ws[wid] = x;
    __syncthreads();
    if (wid == 0) {
        int s = ws[lane];
        #pragma unroll
        for (int o = 1; o < 32; o <<= 1) {
            int t = __shfl_up_sync(0xFFFFFFFFu, s, o);
            if (lane >= o) s += t;
        }
        ws[lane] = s;
    }
    __syncthreads();
    if (i < N_NODES) {
        int excl = g_bofs[blockIdx.x] + x - v + (wid > 0 ? ws[wid - 1] : 0);
        g_off[i] = excl;
        g_cur[i] = excl;
    }
}

__global__ void scatter_kernel(const int* __restrict__ src, const int* __restrict__ dst) {
    int i = blockIdx.x * blockDim.x + threadIdx.x;
    if (i < N_EDGES) {
        int p = atomicAdd(&g_cur[dst[i]], 1);
        g_srcs[p] = src[i];
    }
}

// pad x [N,126] fp32 -> g_fh [N,64] packed fp16
__global__ void pad_x_kernel(const float* __restrict__ x) {
    int i = blockIdx.x * blockDim.x + threadIdx.x;
    if (i < N_NODES * 64) {
        int n = i >> 6, p = i & 63;
        float2 v = make_float2(0.f, 0.f);
        if (p < 63) v = *(const float2*)&x[n * IN_DIM + 2 * p];
        __half2 h = __floats2half2_rn(v.x, v.y);
        g_fh[i] = *(uint32_t*)&h;
    }
}

__global__ void gstart_kernel(const int* __restrict__ batch) {
    int i = blockIdx.x * blockDim.x + threadIdx.x;
    if (i >= N_NODES) return;
    int b = batch[i];
    int bp = (i == 0) ? -1 : batch[i - 1];
    for (int gg = bp + 1; gg <= b; gg++) g_gstart[gg] = i;
    if (i == N_NODES - 1)
        for (int gg = b + 1; gg <= N_GRAPHS; gg++) g_gstart[gg] = N_NODES;
}

// ---------------- weight pre-split: fp32 [K,128] -> packed half2 ------------
__global__ void wsplit_kernel(const float* __restrict__ w1a, const float* __restrict__ w2a,
                              const float* __restrict__ w1b, const float* __restrict__ w2b,
                              const float* __restrict__ w1c, const float* __restrict__ w2c,
                              int Kw1) {
    int slot = blockIdx.y;
    const float* w = (slot == 0) ? w1a : (slot == 1) ? w2a : (slot == 2) ? w1b
                   : (slot == 3) ? w2b : (slot == 4) ? w1c : w2c;
    int Kw = (slot == 0) ? Kw1 : DIMH;
    int i = blockIdx.x * blockDim.x + threadIdx.x;
    if (i >= KPAIRS * 128) return;
    int kp = i >> 7, n = i & 127;
    int k0 = 2 * kp, k1 = k0 + 1;
    float v0 = (k0 < Kw) ? w[k0 * DIMH + n] : 0.0f;
    float v1 = (k1 < Kw) ? w[k1 * DIMH + n] : 0.0f;
    __half2 h = __floats2half2_rn(v0, v1);
    g_wsp[slot * KPAIRS * 128 + i] = *(uint32_t*)&h;
}

// ---------------- aggregation: warp/node over fp16 feat (R10 form, unroll 8)
__global__ __launch_bounds__(256) void agg_kernel(const uint32_t* __restrict__ F,
                                                  uint32_t* __restrict__ oh,
                                                  uint32_t* __restrict__ ol) {
    int warp = (blockIdx.x * blockDim.x + threadIdx.x) >> 5;
    int lane = threadIdx.x & 31;
    if (warp >= N_NODES) return;
    int s = g_off[warp], e = g_off[warp + 1];
    float4 acc;
    {
        uint2 v = *(const uint2*)&F[warp * KPAIRS + 2 * lane];
        float2 a = __half22float2(*(__half2*)&v.x);
        float2 b = __half22float2(*(__half2*)&v.y);
        acc = make_float4(a.x, a.y, b.x, b.y);
    }
    for (int base = s; base < e; base += 32) {
        int cnt = min(32, e - base);
        int idx = (base + lane < e) ? g_srcs[base + lane] : 0;
        int j = 0;
        for (; j + 8 <= cnt; j += 8) {
            uint2 u[8];
            #pragma unroll
            for (int q = 0; q < 8; q++) {
                int sq = __shfl_sync(0xFFFFFFFFu, idx, j + q);
                u[q] = *(const uint2*)&F[sq * KPAIRS + 2 * lane];
            }
            #pragma unroll
            for (int q = 0; q < 8; q++) {
                float2 a = __half22float2(*(__half2*)&u[q].x);
                float2 b = __half22float2(*(__half2*)&u[q].y);
                acc.x += a.x; acc.y += a.y; acc.z += b.x; acc.w += b.y;
            }
        }
        for (; j + 4 <= cnt; j += 4) {
            uint2 u[4];
            #pragma unroll
            for (int q = 0; q < 4; q++) {
                int sq = __shfl_sync(0xFFFFFFFFu, idx, j + q);
                u[q] = *(const uint2*)&F[sq * KPAIRS + 2 * lane];
            }
            #pragma unroll
            for (int q = 0; q < 4; q++) {
                float2 a = __half22float2(*(__half2*)&u[q].x);
                float2 b = __half22float2(*(__half2*)&u[q].y);
                acc.x += a.x; acc.y += a.y; acc.z += b.x; acc.w += b.y;
            }
        }
        for (; j < cnt; j++) {
            int s0 = __shfl_sync(0xFFFFFFFFu, idx, j);
            uint2 u = *(const uint2*)&F[s0 * KPAIRS + 2 * lane];
            float2 a = __half22float2(*(__half2*)&u.x), b = __half22float2(*(__half2*)&u.y);
            acc.x += a.x; acc.y += a.y; acc.z += b.x; acc.w += b.y;
        }
    }
    __half hx = __float2half_rn(acc.x), hy = __float2half_rn(acc.y);
    __half hz = __float2half_rn(acc.z), hw = __float2half_rn(acc.w);
    __half2 h0 = __halves2half2(hx, hy), h1 = __halves2half2(hz, hw);
    __half2 l0 = __floats2half2_rn(acc.x - __half2float(hx), acc.y - __half2float(hy));
    __half2 l1 = __floats2half2_rn(acc.z - __half2float(hz), acc.w - __half2float(hw));
    uint2 hv = make_uint2(*(uint32_t*)&h0, *(uint32_t*)&h1);
    uint2 lv = make_uint2(*(uint32_t*)&l0, *(uint32_t*)&l1);
    *(uint2*)&oh[warp * KPAIRS + 2 * lane] = hv;
    *(uint2*)&ol[warp * KPAIRS + 2 * lane] = lv;
}

// ---------------- fp16 helpers ----------------
__device__ __forceinline__ uint32_t pack_f16x2(__half a, __half b) {
    __half2 p = __halves2half2(a, b);
    return *(uint32_t*)&p;
}
__device__ __forceinline__ void mma_f16(float* c, const uint32_t* a, const uint32_t* b) {
    asm volatile(
        "mma.sync.aligned.m16n8k16.row.col.f32.f16.f16.f32 "
        "{%0,%1,%2,%3}, {%4,%5,%6,%7}, {%8,%9}, {%0,%1,%2,%3};\n"
        : "+f"(c[0]), "+f"(c[1]), "+f"(c[2]), "+f"(c[3])
        : "r"(a[0]), "r"(a[1]), "r"(a[2]), "r"(a[3]), "r"(b[0]), "r"(b[1]));
}

// ---------------- fused double-GEMM per GIN layer, 64-row tile, fp16 --------
#define AST 20
#define BST 136
#define HST 68
#define SM_AH 0
#define SM_AL (64 * AST)
#define SM_B  (2 * 64 * AST)
#define SM_HH (SM_B + 16 * BST)
#define SM_HL (SM_HH + 64 * HST)
#define SMEM_U32 (SM_HH + 2 * 64 * HST)

__global__ __launch_bounds__(256, 3) void layer_gemm_kernel(
    const uint32_t* __restrict__ Ahg, const uint32_t* __restrict__ Alg,
    const uint32_t* __restrict__ W1p, const float* __restrict__ b1,
    const float* __restrict__ gamma, const float* __restrict__ beta,
    const float* __restrict__ mean, const float* __restrict__ var,
    const uint32_t* __restrict__ W2p, const float* __restrict__ b2,
    uint32_t* __restrict__ OUT16)
{
    extern __shared__ uint32_t sm[];
    uint32_t* Ah = sm + SM_AH;
    uint32_t* Al = sm + SM_AL;
    uint32_t* B  = sm + SM_B;
    uint32_t* Hh = sm + SM_HH;
    uint32_t* Hl = sm + SM_HL;

    const int tid  = threadIdx.x;
    const int wid  = tid >> 5;
    const int lane = tid & 31;
    const int g    = lane >> 2;
    const int tig  = lane & 3;
    const int wm   = wid & 1;
    const int wn   = wid >> 1;
    const int row0 = blockIdx.x * 64;

    float acc[2][4][4];

    // =========== GEMM1 ===========
    #pragma unroll
    for (int mi = 0; mi < 2; mi++)
        #pragma unroll
        for (int ni = 0; ni < 4; ni++)
            #pragma unroll
            for (int r = 0; r < 4; r++) acc[mi][ni][r] = 0.0f;

    for (int c = 0; c < 4; c++) {
        {
            int r = tid >> 2, kp4 = (tid & 3) * 4;
            int gr = row0 + r;
            uint4 vh = make_uint4(0, 0, 0, 0), vl = make_uint4(0, 0, 0, 0);
            if (gr < N_NODES) {
                vh = *(const uint4*)&Ahg[gr * KPAIRS + c * 16 + kp4];
                vl = *(const uint4*)&Alg[gr * KPAIRS + c * 16 + kp4];
            }
            *(uint4*)&Ah[r * AST + kp4] = vh;
            *(uint4*)&Al[r * AST + kp4] = vl;
        }
        #pragma unroll
        for (int l = 0; l < 2; l++) {
            int idx = tid + l * 256;
            int kp = idx >> 5;
            int c4 = (idx & 31) * 4;
            uint4 v = *(const uint4*)&W1p[(c * 16 + kp) * 128 + c4];
            *(uint4*)&B[kp * BST + c4] = v;
        }
        __syncthreads();

        #pragma unroll
        for (int ks = 0; ks < 2; ks++) {
            const int kk2 = ks * 8;
            uint32_t a_hi[2][4], a_lo[2][4];
            #pragma unroll
            for (int mi = 0; mi < 2; mi++) {
                int rm = wm * 32 + mi * 16;
                a_hi[mi][0] = Ah[(rm + g    ) * AST + kk2 + tig    ];
                a_hi[mi][1] = Ah[(rm + g + 8) * AST + kk2 + tig    ];
                a_hi[mi][2] = Ah[(rm + g    ) * AST + kk2 + tig + 4];
                a_hi[mi][3] = Ah[(rm + g + 8) * AST + kk2 + tig + 4];
                a_lo[mi][0] = Al[(rm + g    ) * AST + kk2 + tig    ];
                a_lo[mi][1] = Al[(rm + g + 8) * AST + kk2 + tig    ];
                a_lo[mi][2] = Al[(rm + g    ) * AST + kk2 + tig + 4];
                a_lo[mi][3] = Al[(rm + g + 8) * AST + kk2 + tig + 4];
            }
            #pragma unroll
            for (int ni = 0; ni < 4; ni++) {
                int cn = wn * 32 + ni * 8;
                uint32_t b[2];
                b[0] = B[(kk2 + tig    ) * BST + cn + g];
                b[1] = B[(kk2 + tig + 4) * BST + cn + g];
                #pragma unroll
                for (int mi = 0; mi < 2; mi++) {
                    mma_f16(acc[mi][ni], a_hi[mi], b);
                    mma_f16(acc[mi][ni], a_lo[mi], b);
                }
            }
        }
        __syncthreads();
    }

    // ---- epilogue1: BN+ReLU, split hi/lo -> Hh/Hl ----
    {
        float sc[4][2], sh[4][2];
        #pragma unroll
        for (int ni = 0; ni < 4; ni++) {
            #pragma unroll
            for (int j = 0; j < 2; j++) {
                int col = wn * 32 + ni * 8 + 2 * tig + j;
                float s = gamma[col] * rsqrtf(var[col] + BN_EPS);
                sc[ni][j] = s;
                sh[ni][j] = beta[col] - mean[col] * s + b1[col] * s;
            }
        }
        #pragma unroll
        for (int mi = 0; mi < 2; mi++) {
            int r0 = wm * 32 + mi * 16 + g;
            int r1 = r0 + 8;
            #pragma unroll
            for (int ni = 0; ni < 4; ni++) {
                int kp = wn * 16 + ni * 4 + tig;
                float o00 = fmaxf(acc[mi][ni][0] * sc[ni][0] + sh[ni][0], 0.0f);
                float o01 = fmaxf(acc[mi][ni][1] * sc[ni][1] + sh[ni][1], 0.0f);
                float o10 = fmaxf(acc[mi][ni][2] * sc[ni][0] + sh[ni][0], 0.0f);
                float o11 = fmaxf(acc[mi][ni][3] * sc[ni][1] + sh[ni][1], 0.0f);
                __half h00 = __float2half_rn(o00), h01 = __float2half_rn(o01);
                __half h10 = __float2half_rn(o10), h11 = __float2half_rn(o11);
                __half2 l0 = __floats2half2_rn(o00 - __half2float(h00),
                                               o01 - __half2float(h01));
                __half2 l1 = __floats2half2_rn(o10 - __half2float(h10),
                                               o11 - __half2float(h11));
                Hh[r0 * HST + kp] = pack_f16x2(h00, h01);
                Hl[r0 * HST + kp] = *(uint32_t*)&l0;
                Hh[r1 * HST + kp] = pack_f16x2(h10, h11);
                Hl[r1 * HST + kp] = *(uint32_t*)&l1;
            }
        }
    }

    // =========== GEMM2 ===========
    #pragma unroll
    for (int mi = 0; mi < 2; mi++)
        #pragma unroll
        for (int ni = 0; ni < 4; ni++)
            #pragma unroll
            for (int r = 0; r < 4; r++) acc[mi][ni][r] = 0.0f;

    for (int c = 0; c < 4; c++) {
        __syncthreads();
        #pragma unroll
        for (int l = 0; l < 2; l++) {
            int idx = tid + l * 256;
            int kp = idx >> 5;
            int c4 = (idx & 31) * 4;
            uint4 v = *(const uint4*)&W2p[(c * 16 + kp) * 128 + c4];
            *(uint4*)&B[kp * BST + c4] = v;
        }
        __syncthreads();

        #pragma unroll
        for (int ks = 0; ks < 2; ks++) {
            const int kp0 = c * 16 + ks * 8;
            uint32_t a_hi[2][4], a_lo[2][4];
            #pragma unroll
            for (int mi = 0; mi < 2; mi++) {
                int rm = wm * 32 + mi * 16;
                a_hi[mi][0] = Hh[(rm + g    ) * HST + kp0 + tig    ];
                a_hi[mi][1] = Hh[(rm + g + 8) * HST + kp0 + tig    ];
                a_hi[mi][2] = Hh[(rm + g    ) * HST + kp0 + tig + 4];
                a_hi[mi][3] = Hh[(rm + g + 8) * HST + kp0 + tig + 4];
                a_lo[mi][0] = Hl[(rm + g    ) * HST + kp0 + tig    ];
                a_lo[mi][1] = Hl[(rm + g + 8) * HST + kp0 + tig    ];
                a_lo[mi][2] = Hl[(rm + g    ) * HST + kp0 + tig + 4];
                a_lo[mi][3] = Hl[(rm + g + 8) * HST + kp0 + tig + 4];
            }
            const int kb = ks * 8;
            #pragma unroll
            for (int ni = 0; ni < 4; ni++) {
                int cn = wn * 32 + ni * 8;
                uint32_t b[2];
                b[0] = B[(kb + tig    ) * BST + cn + g];
                b[1] = B[(kb + tig + 4) * BST + cn + g];
                #pragma unroll
                for (int mi = 0; mi < 2; mi++) {
                    mma_f16(acc[mi][ni], a_hi[mi], b);
                    mma_f16(acc[mi][ni], a_lo[mi], b);
                }
            }
        }
    }

    // ---- epilogue2: bias + ReLU -> packed fp16 OUT ----
    float bb[4][2];
    #pragma unroll
    for (int ni = 0; ni < 4; ni++) {
        #pragma unroll
        for (int j = 0; j < 2; j++)
            bb[ni][j] = b2[wn * 32 + ni * 8 + 2 * tig + j];
    }
    #pragma unroll
    for (int mi = 0; mi < 2; mi++) {
        int r0 = row0 + wm * 32 + mi * 16 + g;
        int r1 = r0 + 8;
        #pragma unroll
        for (int ni = 0; ni < 4; ni++) {
            int c0 = wn * 32 + ni * 8 + 2 * tig;   // even
            int kp = c0 >> 1;
            if (r0 < N_NODES) {
                __half2 o = __floats2half2_rn(
                    fmaxf(acc[mi][ni][0] + bb[ni][0], 0.0f),
                    fmaxf(acc[mi][ni][1] + bb[ni][1], 0.0f));
                OUT16[r0 * KPAIRS + kp] = *(uint32_t*)&o;
            }
            if (r1 < N_NODES) {
                __half2 o = __floats2half2_rn(
                    fmaxf(acc[mi][ni][2] + bb[ni][0], 0.0f),
                    fmaxf(acc[mi][ni][3] + bb[ni][1], 0.0f));
                OUT16[r1 * KPAIRS + kp] = *(uint32_t*)&o;
            }
        }
    }
}

// ---------------- segment pooling over fp16 features ------------------------
__global__ void pool_seg_kernel(const uint32_t* __restrict__ h, float* __restrict__ pool) {
    int gph = blockIdx.x;
    int t = threadIdx.x;       // 0..127 -> feature t
    int u = t >> 1, hi = t & 1;
    int s = g_gstart[gph], e = g_gstart[gph + 1];
    float a0 = 0.f, a1 = 0.f;
    int r = s;
    for (; r + 2 <= e; r += 2) {
        uint32_t v0 = h[r * KPAIRS + u];
        uint32_t v1 = h[(r + 1) * KPAIRS + u];
        float2 f0 = __half22float2(*(__half2*)&v0);
        float2 f1 = __half22float2(*(__half2*)&v1);
        a0 += hi ? f0.y : f0.x;
        a1 += hi ? f1.y : f1.x;
    }
    if (r < e) {
        uint32_t v = h[r * KPAIRS + u];
        float2 f = __half22float2(*(__half2*)&v);
        a0 += hi ? f.y : f.x;
    }
    pool[gph * DIMH + t] = a0 + a1;
}

// ---------------- head ----------------
__global__ void head_kernel(const float* __restrict__ pool,
                            const float* __restrict__ l1w, const float* __restrict__ l1b,
                            const float* __restrict__ l2w, const float* __restrict__ l2b,
                            float* __restrict__ out) {
    __shared__ float hg[DIMH];
    __shared__ float o1[LIN1_DIM];
    int gph = blockIdx.x;
    int t = threadIdx.x;  // 128
    hg[t] = pool[gph * DIMH + t];
    __syncthreads();
    if (t < LIN1_DIM) {
        float s = l1b[t];
        #pragma unroll 8
        for (int k = 0; k < DIMH; k++) s += hg[k] * l1w[k * LIN1_DIM + t];
        o1[t] = fmaxf(s, 0.0f);
    }
    __syncthreads();
    if (t == 0) {
        float s = l2b[0];
        #pragma unroll 8
        for (int j = 0; j < LIN1_DIM; j++) s += o1[j] * l2w[j];
        out[gph] = 1.0f / (1.0f + expf(-s));
    }
}

// ---------------- launch ----------------
extern "C" void kernel_launch(void* const* d_in, const int* in_sizes, int n_in,
                              void* d_out, int out_size) {
    const float* x          = (const float*)d_in[0];
    const int*   edge_index = (const int*)d_in[1];
    const int*   batch      = (const int*)d_in[2];
    const float* w[3][7];
    const float* b2[3];
    for (int l = 0; l < 3; l++) {
        int base = 3 + l * 8;
        w[l][0] = (const float*)d_in[base + 0];
        w[l][1] = (const float*)d_in[base + 1];
        w[l][2] = (const float*)d_in[base + 2];
        w[l][3] = (const float*)d_in[base + 3];
        w[l][4] = (const float*)d_in[base + 4];
        w[l][5] = (const float*)d_in[base + 5];
        w[l][6] = (const float*)d_in[base + 6];
        b2[l]   = (const float*)d_in[base + 7];
    }
    const float* l1w = (const float*)d_in[27];
    const float* l1b = (const float*)d_in[28];
    const float* l2w = (const float*)d_in[29];
    const float* l2b = (const float*)d_in[30];
    float* out = (float*)d_out;

    const int* e_src = edge_index;
    const int* e_dst = edge_index + N_EDGES;

    static uint32_t* p_fh   = nullptr;
    static uint32_t* p_ah   = nullptr;
    static uint32_t* p_al   = nullptr;
    static uint32_t* p_wsp  = nullptr;
    static int*      p_cnt  = nullptr;
    static float*    p_pool = nullptr;
    if (!p_fh) {
        cudaGetSymbolAddress((void**)&p_fh,   g_fh);
        cudaGetSymbolAddress((void**)&p_ah,   g_ah);
        cudaGetSymbolAddress((void**)&p_al,   g_al);
        cudaGetSymbolAddress((void**)&p_wsp,  g_wsp);
        cudaGetSymbolAddress((void**)&p_cnt,  g_cnt);
        cudaGetSymbolAddress((void**)&p_pool, g_pool);
        cudaFuncSetAttribute(layer_gemm_kernel,
                             cudaFuncAttributeMaxDynamicSharedMemorySize,
                             SMEM_U32 * 4);
    }

    // ---- setup kernels first (independent of CSR) ----
    pad_x_kernel<<<(N_NODES * 64 + 255) / 256, 256>>>(x);
    gstart_kernel<<<(N_NODES + 255) / 256, 256>>>(batch);
    {
        dim3 grid((KPAIRS * 128 + 255) / 256, 6);
        wsplit_kernel<<<grid, 256>>>(w[0][0], w[0][6], w[1][0], w[1][6],
                                     w[2][0], w[2][6], IN_DIM);
    }

    // ---- CSR build ----
    cudaMemsetAsync(p_cnt, 0, N_NODES * sizeof(int));
    count_kernel<<<(N_EDGES + 255) / 256, 256>>>(e_dst);
    block_sum_kernel<<<SCAN_NB, 1024>>>();
    scan_sums_kernel<<<1, 64>>>();
    block_scan_kernel<<<SCAN_NB, 1024>>>();
    scatter_kernel<<<(N_EDGES + 255) / 256, 256>>>(e_src, e_dst);

    const int GEMM_GRID = (N_NODES + 63) / 64;
    const int AGG_GRID  = (N_NODES * 32 + 255) / 256;
    const size_t SMEM   = SMEM_U32 * 4;

    // ---- 3 GIN layers ----
    for (int l = 0; l < 3; l++) {
        agg_kernel<<<AGG_GRID, 256>>>(p_fh, p_ah, p_al);
        layer_gemm_kernel<<<GEMM_GRID, 256, SMEM>>>(
            p_ah, p_al,
            p_wsp + (2 * l) * KPAIRS * 128, w[l][1], w[l][2], w[l][3],
            w[l][4], w[l][5],
            p_wsp + (2 * l + 1) * KPAIRS * 128, b2[l],
            p_fh);
    }

    // ---- pool + head ----
    pool_seg_kernel<<<N_GRAPHS, 128>>>(p_fh, p_pool);
    head_kernel<<<N_GRAPHS, 128>>>(p_pool, l1w, l1b, l2w, l2b, out);
}

// round 13
// speedup vs baseline: 1.0919x; 1.0290x over previous
#include <cuda_runtime.h>
#include <cuda_fp16.h>
#include <math.h>
#include <stdint.h>

#define N_NODES 50000
#define N_EDGES 800000
#define N_GRAPHS 512
#define IN_DIM 126
#define DIMH 128
#define LIN1_DIM 64
#define BN_EPS 1e-5f

#define SCAN_NB 49   // ceil(50000/1024)
#define KPAIRS 64    // 128 k / 2 per u32

// ---------------- device scratch ----------------
__device__ uint32_t g_fh[N_NODES * KPAIRS];    // features, packed fp16 (half2)
__device__ uint32_t g_ah[N_NODES * KPAIRS];    // agg output hi plane
__device__ uint32_t g_al[N_NODES * KPAIRS];    // agg output lo (residual) plane
__device__ uint32_t g_wsp[6 * KPAIRS * 128];   // pre-split fp16 weights, slot-major
__device__ int      g_cnt[N_NODES + 64];       // counts + 64 tail flags (zeroed per call)
__device__ int      g_bval[64];                // block totals (flag-protected)
__device__ int      g_off[N_NODES + 1];
__device__ int      g_cur[N_NODES];
__device__ int      g_srcs[N_EDGES];
__device__ float    g_pool[N_GRAPHS * DIMH];
__device__ int      g_gstart[N_GRAPHS + 1];

// ---------------- CSR build ----------------
__global__ void count_kernel(const int* __restrict__ dst) {
    int i = blockIdx.x * blockDim.x + threadIdx.x;
    if (i < N_EDGES) atomicAdd(&g_cnt[dst[i]], 1);
}

// single-pass exclusive scan (49 blocks x 1024, all resident -> safe lookback)
__global__ void scan_onepass_kernel() {
    __shared__ int ws[32];
    __shared__ int s_prefix;
    const int b = blockIdx.x;
    int i = b * 1024 + threadIdx.x;
    int lane = threadIdx.x & 31, wid = threadIdx.x >> 5;
    int v = (i < N_NODES) ? g_cnt[i] : 0;
    int x = v;
    #pragma unroll
    for (int o = 1; o < 32; o <<= 1) {
        int t = __shfl_up_sync(0xFFFFFFFFu, x, o);
        if (lane >= o) x += t;
    }
    if (lane == 31) ws[wid] = x;
    __syncthreads();
    if (wid == 0) {
        int s = ws[lane];
        #pragma unroll
        for (int o = 1; o < 32; o <<= 1) {
            int t = __shfl_up_sync(0xFFFFFFFFu, s, o);
            if (lane >= o) s += t;
        }
        ws[lane] = s;
    }
    __syncthreads();
    int incl  = x + (wid > 0 ? ws[wid - 1] : 0);   // block-local inclusive
    int total = ws[31];                            // block total

    // publish total with release flag
    if (threadIdx.x == 0) {
        g_bval[b] = total;
        __threadfence();
        atomicExch(&g_cnt[N_NODES + b], 1);
        s_prefix = 0;
    }
    __syncthreads();
    // parallel lookback over earlier blocks
    if (threadIdx.x < b) {
        while (atomicAdd(&g_cnt[N_NODES + threadIdx.x], 0) == 0) { }
        atomicAdd(&s_prefix, g_bval[threadIdx.x]);
    }
    __syncthreads();
    int excl = s_prefix + incl - v;
    if (i < N_NODES) { g_off[i] = excl; g_cur[i] = excl; }
    if (b == SCAN_NB - 1 && threadIdx.x == 0)
        g_off[N_NODES] = s_prefix + total;
}

__global__ void scatter_kernel(const int* __restrict__ src, const int* __restrict__ dst) {
    int i = blockIdx.x * blockDim.x + threadIdx.x;
    if (i < N_EDGES) {
        int p = atomicAdd(&g_cur[dst[i]], 1);
        g_srcs[p] = src[i];
    }
}

// pad x [N,126] fp32 -> g_fh [N,64] packed fp16
__global__ void pad_x_kernel(const float* __restrict__ x) {
    int i = blockIdx.x * blockDim.x + threadIdx.x;
    if (i < N_NODES * 64) {
        int n = i >> 6, p = i & 63;
        float2 v = make_float2(0.f, 0.f);
        if (p < 63) v = *(const float2*)&x[n * IN_DIM + 2 * p];
        __half2 h = __floats2half2_rn(v.x, v.y);
        g_fh[i] = *(uint32_t*)&h;
    }
}

__global__ void gstart_kernel(const int* __restrict__ batch) {
    int i = blockIdx.x * blockDim.x + threadIdx.x;
    if (i >= N_NODES) return;
    int b = batch[i];
    int bp = (i == 0) ? -1 : batch[i - 1];
    for (int gg = bp + 1; gg <= b; gg++) g_gstart[gg] = i;
    if (i == N_NODES - 1)
        for (int gg = b + 1; gg <= N_GRAPHS; gg++) g_gstart[gg] = N_NODES;
}

// ---------------- weight pre-split: fp32 [K,128] -> packed half2 ------------
__global__ void wsplit_kernel(const float* __restrict__ w1a, const float* __restrict__ w2a,
                              const float* __restrict__ w1b, const float* __restrict__ w2b,
                              const float* __restrict__ w1c, const float* __restrict__ w2c,
                              int Kw1) {
    int slot = blockIdx.y;
    const float* w = (slot == 0) ? w1a : (slot == 1) ? w2a : (slot == 2) ? w1b
                   : (slot == 3) ? w2b : (slot == 4) ? w1c : w2c;
    int Kw = (slot == 0) ? Kw1 : DIMH;
    int i = blockIdx.x * blockDim.x + threadIdx.x;
    if (i >= KPAIRS * 128) return;
    int kp = i >> 7, n = i & 127;
    int k0 = 2 * kp, k1 = k0 + 1;
    float v0 = (k0 < Kw) ? w[k0 * DIMH + n] : 0.0f;
    float v1 = (k1 < Kw) ? w[k1 * DIMH + n] : 0.0f;
    __half2 h = __floats2half2_rn(v0, v1);
    g_wsp[slot * KPAIRS * 128 + i] = *(uint32_t*)&h;
}

// ---------------- aggregation: warp/node over fp16 feat (R10-proven) --------
__global__ __launch_bounds__(256) void agg_kernel(const uint32_t* __restrict__ F,
                                                  uint32_t* __restrict__ oh,
                                                  uint32_t* __restrict__ ol) {
    int warp = (blockIdx.x * blockDim.x + threadIdx.x) >> 5;
    int lane = threadIdx.x & 31;
    if (warp >= N_NODES) return;
    int s = g_off[warp], e = g_off[warp + 1];
    float4 acc;
    {
        uint2 v = *(const uint2*)&F[warp * KPAIRS + 2 * lane];
        float2 a = __half22float2(*(__half2*)&v.x);
        float2 b = __half22float2(*(__half2*)&v.y);
        acc = make_float4(a.x, a.y, b.x, b.y);
    }
    for (int base = s; base < e; base += 32) {
        int cnt = min(32, e - base);
        int idx = (base + lane < e) ? g_srcs[base + lane] : 0;
        int j = 0;
        for (; j + 4 <= cnt; j += 4) {
            int s0 = __shfl_sync(0xFFFFFFFFu, idx, j);
            int s1 = __shfl_sync(0xFFFFFFFFu, idx, j + 1);
            int s2 = __shfl_sync(0xFFFFFFFFu, idx, j + 2);
            int s3 = __shfl_sync(0xFFFFFFFFu, idx, j + 3);
            uint2 u0 = *(const uint2*)&F[s0 * KPAIRS + 2 * lane];
            uint2 u1 = *(const uint2*)&F[s1 * KPAIRS + 2 * lane];
            uint2 u2 = *(const uint2*)&F[s2 * KPAIRS + 2 * lane];
            uint2 u3 = *(const uint2*)&F[s3 * KPAIRS + 2 * lane];
            float2 a0 = __half22float2(*(__half2*)&u0.x), b0 = __half22float2(*(__half2*)&u0.y);
            float2 a1 = __half22float2(*(__half2*)&u1.x), b1 = __half22float2(*(__half2*)&u1.y);
            float2 a2 = __half22float2(*(__half2*)&u2.x), b2 = __half22float2(*(__half2*)&u2.y);
            float2 a3 = __half22float2(*(__half2*)&u3.x), b3 = __half22float2(*(__half2*)&u3.y);
            acc.x += (a0.x + a1.x) + (a2.x + a3.x);
            acc.y += (a0.y + a1.y) + (a2.y + a3.y);
            acc.z += (b0.x + b1.x) + (b2.x + b3.x);
            acc.w += (b0.y + b1.y) + (b2.y + b3.y);
        }
        for (; j < cnt; j++) {
            int s0 = __shfl_sync(0xFFFFFFFFu, idx, j);
            uint2 u = *(const uint2*)&F[s0 * KPAIRS + 2 * lane];
            float2 a = __half22float2(*(__half2*)&u.x), b = __half22float2(*(__half2*)&u.y);
            acc.x += a.x; acc.y += a.y; acc.z += b.x; acc.w += b.y;
        }
    }
    __half hx = __float2half_rn(acc.x), hy = __float2half_rn(acc.y);
    __half hz = __float2half_rn(acc.z), hw = __float2half_rn(acc.w);
    __half2 h0 = __halves2half2(hx, hy), h1 = __halves2half2(hz, hw);
    __half2 l0 = __floats2half2_rn(acc.x - __half2float(hx), acc.y - __half2float(hy));
    __half2 l1 = __floats2half2_rn(acc.z - __half2float(hz), acc.w - __half2float(hw));
    uint2 hv = make_uint2(*(uint32_t*)&h0, *(uint32_t*)&h1);
    uint2 lv = make_uint2(*(uint32_t*)&l0, *(uint32_t*)&l1);
    *(uint2*)&oh[warp * KPAIRS + 2 * lane] = hv;
    *(uint2*)&ol[warp * KPAIRS + 2 * lane] = lv;
}

// ---------------- fp16 helpers ----------------
__device__ __forceinline__ uint32_t pack_f16x2(__half a, __half b) {
    __half2 p = __halves2half2(a, b);
    return *(uint32_t*)&p;
}
__device__ __forceinline__ void mma_f16(float* c, const uint32_t* a, const uint32_t* b) {
    asm volatile(
        "mma.sync.aligned.m16n8k16.row.col.f32.f16.f16.f32 "
        "{%0,%1,%2,%3}, {%4,%5,%6,%7}, {%8,%9}, {%0,%1,%2,%3};\n"
        : "+f"(c[0]), "+f"(c[1]), "+f"(c[2]), "+f"(c[3])
        : "r"(a[0]), "r"(a[1]), "r"(a[2]), "r"(a[3]), "r"(b[0]), "r"(b[1]));
}

// ---------------- fused double-GEMM per GIN layer, 64-row tile, fp16 --------
#define AST 20
#define BST 136
#define HST 68
#define SM_AH 0
#define SM_AL (64 * AST)
#define SM_B  (2 * 64 * AST)
#define SM_HH (SM_B + 16 * BST)
#define SM_HL (SM_HH + 64 * HST)
#define SMEM_U32 (SM_HH + 2 * 64 * HST)

__global__ __launch_bounds__(256, 3) void layer_gemm_kernel(
    const uint32_t* __restrict__ Ahg, const uint32_t* __restrict__ Alg,
    const uint32_t* __restrict__ W1p, const float* __restrict__ b1,
    const float* __restrict__ gamma, const float* __restrict__ beta,
    const float* __restrict__ mean, const float* __restrict__ var,
    const uint32_t* __restrict__ W2p, const float* __restrict__ b2,
    uint32_t* __restrict__ OUT16)
{
    extern __shared__ uint32_t sm[];
    uint32_t* Ah = sm + SM_AH;
    uint32_t* Al = sm + SM_AL;
    uint32_t* B  = sm + SM_B;
    uint32_t* Hh = sm + SM_HH;
    uint32_t* Hl = sm + SM_HL;

    const int tid  = threadIdx.x;
    const int wid  = tid >> 5;
    const int lane = tid & 31;
    const int g    = lane >> 2;
    const int tig  = lane & 3;
    const int wm   = wid & 1;
    const int wn   = wid >> 1;
    const int row0 = blockIdx.x * 64;

    float acc[2][4][4];

    // =========== GEMM1 ===========
    #pragma unroll
    for (int mi = 0; mi < 2; mi++)
        #pragma unroll
        for (int ni = 0; ni < 4; ni++)
            #pragma unroll
            for (int r = 0; r < 4; r++) acc[mi][ni][r] = 0.0f;

    for (int c = 0; c < 4; c++) {
        {
            int r = tid >> 2, kp4 = (tid & 3) * 4;
            int gr = row0 + r;
            uint4 vh = make_uint4(0, 0, 0, 0), vl = make_uint4(0, 0, 0, 0);
            if (gr < N_NODES) {
                vh = *(const uint4*)&Ahg[gr * KPAIRS + c * 16 + kp4];
                vl = *(const uint4*)&Alg[gr * KPAIRS + c * 16 + kp4];
            }
            *(uint4*)&Ah[r * AST + kp4] = vh;
            *(uint4*)&Al[r * AST + kp4] = vl;
        }
        #pragma unroll
        for (int l = 0; l < 2; l++) {
            int idx = tid + l * 256;
            int kp = idx >> 5;
            int c4 = (idx & 31) * 4;
            uint4 v = *(const uint4*)&W1p[(c * 16 + kp) * 128 + c4];
            *(uint4*)&B[kp * BST + c4] = v;
        }
        __syncthreads();

        #pragma unroll
        for (int ks = 0; ks < 2; ks++) {
            const int kk2 = ks * 8;
            uint32_t a_hi[2][4], a_lo[2][4];
            #pragma unroll
            for (int mi = 0; mi < 2; mi++) {
                int rm = wm * 32 + mi * 16;
                a_hi[mi][0] = Ah[(rm + g    ) * AST + kk2 + tig    ];
                a_hi[mi][1] = Ah[(rm + g + 8) * AST + kk2 + tig    ];
                a_hi[mi][2] = Ah[(rm + g    ) * AST + kk2 + tig + 4];
                a_hi[mi][3] = Ah[(rm + g + 8) * AST + kk2 + tig + 4];
                a_lo[mi][0] = Al[(rm + g    ) * AST + kk2 + tig    ];
                a_lo[mi][1] = Al[(rm + g + 8) * AST + kk2 + tig    ];
                a_lo[mi][2] = Al[(rm + g    ) * AST + kk2 + tig + 4];
                a_lo[mi][3] = Al[(rm + g + 8) * AST + kk2 + tig + 4];
            }
            #pragma unroll
            for (int ni = 0; ni < 4; ni++) {
                int cn = wn * 32 + ni * 8;
                uint32_t b[2];
                b[0] = B[(kk2 + tig    ) * BST + cn + g];
                b[1] = B[(kk2 + tig + 4) * BST + cn + g];
                #pragma unroll
                for (int mi = 0; mi < 2; mi++) {
                    mma_f16(acc[mi][ni], a_hi[mi], b);
                    mma_f16(acc[mi][ni], a_lo[mi], b);
                }
            }
        }
        __syncthreads();
    }

    // ---- epilogue1: BN+ReLU, split hi/lo -> Hh/Hl ----
    {
        float sc[4][2], sh[4][2];
        #pragma unroll
        for (int ni = 0; ni < 4; ni++) {
            #pragma unroll
            for (int j = 0; j < 2; j++) {
                int col = wn * 32 + ni * 8 + 2 * tig + j;
                float s = gamma[col] * rsqrtf(var[col] + BN_EPS);
                sc[ni][j] = s;
                sh[ni][j] = beta[col] - mean[col] * s + b1[col] * s;
            }
        }
        #pragma unroll
        for (int mi = 0; mi < 2; mi++) {
            int r0 = wm * 32 + mi * 16 + g;
            int r1 = r0 + 8;
            #pragma unroll
            for (int ni = 0; ni < 4; ni++) {
                int kp = wn * 16 + ni * 4 + tig;
                float o00 = fmaxf(acc[mi][ni][0] * sc[ni][0] + sh[ni][0], 0.0f);
                float o01 = fmaxf(acc[mi][ni][1] * sc[ni][1] + sh[ni][1], 0.0f);
                float o10 = fmaxf(acc[mi][ni][2] * sc[ni][0] + sh[ni][0], 0.0f);
                float o11 = fmaxf(acc[mi][ni][3] * sc[ni][1] + sh[ni][1], 0.0f);
                __half h00 = __float2half_rn(o00), h01 = __float2half_rn(o01);
                __half h10 = __float2half_rn(o10), h11 = __float2half_rn(o11);
                __half2 l0 = __floats2half2_rn(o00 - __half2float(h00),
                                               o01 - __half2float(h01));
                __half2 l1 = __floats2half2_rn(o10 - __half2float(h10),
                                               o11 - __half2float(h11));
                Hh[r0 * HST + kp] = pack_f16x2(h00, h01);
                Hl[r0 * HST + kp] = *(uint32_t*)&l0;
                Hh[r1 * HST + kp] = pack_f16x2(h10, h11);
                Hl[r1 * HST + kp] = *(uint32_t*)&l1;
            }
        }
    }

    // =========== GEMM2 ===========
    #pragma unroll
    for (int mi = 0; mi < 2; mi++)
        #pragma unroll
        for (int ni = 0; ni < 4; ni++)
            #pragma unroll
            for (int r = 0; r < 4; r++) acc[mi][ni][r] = 0.0f;

    for (int c = 0; c < 4; c++) {
        __syncthreads();
        #pragma unroll
        for (int l = 0; l < 2; l++) {
            int idx = tid + l * 256;
            int kp = idx >> 5;
            int c4 = (idx & 31) * 4;
            uint4 v = *(const uint4*)&W2p[(c * 16 + kp) * 128 + c4];
            *(uint4*)&B[kp * BST + c4] = v;
        }
        __syncthreads();

        #pragma unroll
        for (int ks = 0; ks < 2; ks++) {
            const int kp0 = c * 16 + ks * 8;
            uint32_t a_hi[2][4], a_lo[2][4];
            #pragma unroll
            for (int mi = 0; mi < 2; mi++) {
                int rm = wm * 32 + mi * 16;
                a_hi[mi][0] = Hh[(rm + g    ) * HST + kp0 + tig    ];
                a_hi[mi][1] = Hh[(rm + g + 8) * HST + kp0 + tig    ];
                a_hi[mi][2] = Hh[(rm + g    ) * HST + kp0 + tig + 4];
                a_hi[mi][3] = Hh[(rm + g + 8) * HST + kp0 + tig + 4];
                a_lo[mi][0] = Hl[(rm + g    ) * HST + kp0 + tig    ];
                a_lo[mi][1] = Hl[(rm + g + 8) * HST + kp0 + tig    ];
                a_lo[mi][2] = Hl[(rm + g    ) * HST + kp0 + tig + 4];
                a_lo[mi][3] = Hl[(rm + g + 8) * HST + kp0 + tig + 4];
            }
            const int kb = ks * 8;
            #pragma unroll
            for (int ni = 0; ni < 4; ni++) {
                int cn = wn * 32 + ni * 8;
                uint32_t b[2];
                b[0] = B[(kb + tig    ) * BST + cn + g];
                b[1] = B[(kb + tig + 4) * BST + cn + g];
                #pragma unroll
                for (int mi = 0; mi < 2; mi++) {
                    mma_f16(acc[mi][ni], a_hi[mi], b);
                    mma_f16(acc[mi][ni], a_lo[mi], b);
                }
            }
        }
    }

    // ---- epilogue2: bias + ReLU -> packed fp16 OUT ----
    float bb[4][2];
    #pragma unroll
    for (int ni = 0; ni < 4; ni++) {
        #pragma unroll
        for (int j = 0; j < 2; j++)
            bb[ni][j] = b2[wn * 32 + ni * 8 + 2 * tig + j];
    }
    #pragma unroll
    for (int mi = 0; mi < 2; mi++) {
        int r0 = row0 + wm * 32 + mi * 16 + g;
        int r1 = r0 + 8;
        #pragma unroll
        for (int ni = 0; ni < 4; ni++) {
            int c0 = wn * 32 + ni * 8 + 2 * tig;   // even
            int kp = c0 >> 1;
            if (r0 < N_NODES) {
                __half2 o = __floats2half2_rn(
                    fmaxf(acc[mi][ni][0] + bb[ni][0], 0.0f),
                    fmaxf(acc[mi][ni][1] + bb[ni][1], 0.0f));
                OUT16[r0 * KPAIRS + kp] = *(uint32_t*)&o;
            }
            if (r1 < N_NODES) {
                __half2 o = __floats2half2_rn(
                    fmaxf(acc[mi][ni][2] + bb[ni][0], 0.0f),
                    fmaxf(acc[mi][ni][3] + bb[ni][1], 0.0f));
                OUT16[r1 * KPAIRS + kp] = *(uint32_t*)&o;
            }
        }
    }
}

// ---------------- segment pooling over fp16 features ------------------------
__global__ void pool_seg_kernel(const uint32_t* __restrict__ h, float* __restrict__ pool) {
    int gph = blockIdx.x;
    int t = threadIdx.x;       // 0..127 -> feature t
    int u = t >> 1, hi = t & 1;
    int s = g_gstart[gph], e = g_gstart[gph + 1];
    float a0 = 0.f, a1 = 0.f;
    int r = s;
    for (; r + 2 <= e; r += 2) {
        uint32_t v0 = h[r * KPAIRS + u];
        uint32_t v1 = h[(r + 1) * KPAIRS + u];
        float2 f0 = __half22float2(*(__half2*)&v0);
        float2 f1 = __half22float2(*(__half2*)&v1);
        a0 += hi ? f0.y : f0.x;
        a1 += hi ? f1.y : f1.x;
    }
    if (r < e) {
        uint32_t v = h[r * KPAIRS + u];
        float2 f = __half22float2(*(__half2*)&v);
        a0 += hi ? f.y : f.x;
    }
    pool[gph * DIMH + t] = a0 + a1;
}

// ---------------- head ----------------
__global__ void head_kernel(const float* __restrict__ pool,
                            const float* __restrict__ l1w, const float* __restrict__ l1b,
                            const float* __restrict__ l2w, const float* __restrict__ l2b,
                            float* __restrict__ out) {
    __shared__ float hg[DIMH];
    __shared__ float o1[LIN1_DIM];
    int gph = blockIdx.x;
    int t = threadIdx.x;  // 128
    hg[t] = pool[gph * DIMH + t];
    __syncthreads();
    if (t < LIN1_DIM) {
        float s = l1b[t];
        #pragma unroll 8
        for (int k = 0; k < DIMH; k++) s += hg[k] * l1w[k * LIN1_DIM + t];
        o1[t] = fmaxf(s, 0.0f);
    }
    __syncthreads();
    if (t == 0) {
        float s = l2b[0];
        #pragma unroll 8
        for (int j = 0; j < LIN1_DIM; j++) s += o1[j] * l2w[j];
        out[gph] = 1.0f / (1.0f + expf(-s));
    }
}

// ---------------- launch ----------------
extern "C" void kernel_launch(void* const* d_in, const int* in_sizes, int n_in,
                              void* d_out, int out_size) {
    const float* x          = (const float*)d_in[0];
    const int*   edge_index = (const int*)d_in[1];
    const int*   batch      = (const int*)d_in[2];
    const float* w[3][7];
    const float* b2[3];
    for (int l = 0; l < 3; l++) {
        int base = 3 + l * 8;
        w[l][0] = (const float*)d_in[base + 0];
        w[l][1] = (const float*)d_in[base + 1];
        w[l][2] = (const float*)d_in[base + 2];
        w[l][3] = (const float*)d_in[base + 3];
        w[l][4] = (const float*)d_in[base + 4];
        w[l][5] = (const float*)d_in[base + 5];
        w[l][6] = (const float*)d_in[base + 6];
        b2[l]   = (const float*)d_in[base + 7];
    }
    const float* l1w = (const float*)d_in[27];
    const float* l1b = (const float*)d_in[28];
    const float* l2w = (const float*)d_in[29];
    const float* l2b = (const float*)d_in[30];
    float* out = (float*)d_out;

    const int* e_src = edge_index;
    const int* e_dst = edge_index + N_EDGES;

    static uint32_t* p_fh   = nullptr;
    static uint32_t* p_ah   = nullptr;
    static uint32_t* p_al   = nullptr;
    static uint32_t* p_wsp  = nullptr;
    static int*      p_cnt  = nullptr;
    static float*    p_pool = nullptr;
    if (!p_fh) {
        cudaGetSymbolAddress((void**)&p_fh,   g_fh);
        cudaGetSymbolAddress((void**)&p_ah,   g_ah);
        cudaGetSymbolAddress((void**)&p_al,   g_al);
        cudaGetSymbolAddress((void**)&p_wsp,  g_wsp);
        cudaGetSymbolAddress((void**)&p_cnt,  g_cnt);
        cudaGetSymbolAddress((void**)&p_pool, g_pool);
        cudaFuncSetAttribute(layer_gemm_kernel,
                             cudaFuncAttributeMaxDynamicSharedMemorySize,
                             SMEM_U32 * 4);
    }

    // ---- CSR build (counts + lookback flags zeroed in one memset) ----
    cudaMemsetAsync(p_cnt, 0, (N_NODES + 64) * sizeof(int));
    count_kernel<<<(N_EDGES + 255) / 256, 256>>>(e_dst);
    scan_onepass_kernel<<<SCAN_NB, 1024>>>();
    scatter_kernel<<<(N_EDGES + 255) / 256, 256>>>(e_src, e_dst);

    // ---- pad x, graph boundaries, weight pre-split ----
    pad_x_kernel<<<(N_NODES * 64 + 255) / 256, 256>>>(x);
    gstart_kernel<<<(N_NODES + 255) / 256, 256>>>(batch);
    {
        dim3 grid((KPAIRS * 128 + 255) / 256, 6);
        wsplit_kernel<<<grid, 256>>>(w[0][0], w[0][6], w[1][0], w[1][6],
                                     w[2][0], w[2][6], IN_DIM);
    }

    const int GEMM_GRID = (N_NODES + 63) / 64;
    const int AGG_GRID  = (N_NODES * 32 + 255) / 256;
    const size_t SMEM   = SMEM_U32 * 4;

    // ---- 3 GIN layers ----
    for (int l = 0; l < 3; l++) {
        agg_kernel<<<AGG_GRID, 256>>>(p_fh, p_ah, p_al);
        layer_gemm_kernel<<<GEMM_GRID, 256, SMEM>>>(
            p_ah, p_al,
            p_wsp + (2 * l) * KPAIRS * 128, w[l][1], w[l][2], w[l][3],
            w[l][4], w[l][5],
            p_wsp + (2 * l + 1) * KPAIRS * 128, b2[l],
            p_fh);
    }

    // ---- pool + head ----
    pool_seg_kernel<<<N_GRAPHS, 128>>>(p_fh, p_pool);
    head_kernel<<<N_GRAPHS, 128>>>(p_pool, l1w, l1b, l2w, l2b, out);
}

// round 14
// speedup vs baseline: 1.0945x; 1.0024x over previous
#include <cuda_runtime.h>
#include <cuda_fp16.h>
#include <math.h>
#include <stdint.h>

#define N_NODES 50000
#define N_EDGES 800000
#define N_GRAPHS 512
#define IN_DIM 126
#define DIMH 128
#define LIN1_DIM 64
#define BN_EPS 1e-5f

#define SCAN_NB 49   // ceil(50000/1024)
#define KPAIRS 64    // 128 k / 2 per u32

// ---------------- device scratch ----------------
__device__ uint32_t g_fh[N_NODES * KPAIRS];    // features, packed fp16 (half2)
__device__ uint32_t g_ah[N_NODES * KPAIRS];    // agg output hi plane
__device__ uint32_t g_al[N_NODES * KPAIRS];    // agg output lo (residual) plane
__device__ uint32_t g_wsp[6 * KPAIRS * 128];   // pre-split fp16 weights, slot-major
__device__ int      g_cnt[N_NODES + 64];       // counts + 64 tail flags (zeroed per call)
__device__ int      g_bval[64];                // block totals (flag-protected)
__device__ int      g_off[N_NODES + 1];
__device__ int      g_cur[N_NODES];
__device__ int      g_srcs[N_EDGES];
__device__ float    g_pool[N_GRAPHS * DIMH];
__device__ int      g_gstart[N_GRAPHS + 1];

// ---------------- CSR build ----------------
__global__ void count_kernel(const int* __restrict__ dst) {
    int i = blockIdx.x * blockDim.x + threadIdx.x;
    if (i < N_EDGES) atomicAdd(&g_cnt[dst[i]], 1);
}

// single-pass exclusive scan (49 blocks x 1024, all resident -> safe lookback)
__global__ void scan_onepass_kernel() {
    __shared__ int ws[32];
    __shared__ int s_prefix;
    const int b = blockIdx.x;
    int i = b * 1024 + threadIdx.x;
    int lane = threadIdx.x & 31, wid = threadIdx.x >> 5;
    int v = (i < N_NODES) ? g_cnt[i] : 0;
    int x = v;
    #pragma unroll
    for (int o = 1; o < 32; o <<= 1) {
        int t = __shfl_up_sync(0xFFFFFFFFu, x, o);
        if (lane >= o) x += t;
    }
    if (lane == 31) ws[wid] = x;
    __syncthreads();
    if (wid == 0) {
        int s = ws[lane];
        #pragma unroll
        for (int o = 1; o < 32; o <<= 1) {
            int t = __shfl_up_sync(0xFFFFFFFFu, s, o);
            if (lane >= o) s += t;
        }
        ws[lane] = s;
    }
    __syncthreads();
    int incl  = x + (wid > 0 ? ws[wid - 1] : 0);
    int total = ws[31];

    if (threadIdx.x == 0) {
        g_bval[b] = total;
        __threadfence();
        atomicExch(&g_cnt[N_NODES + b], 1);
        s_prefix = 0;
    }
    __syncthreads();
    if (threadIdx.x < b) {
        while (atomicAdd(&g_cnt[N_NODES + threadIdx.x], 0) == 0) { }
        atomicAdd(&s_prefix, g_bval[threadIdx.x]);
    }
    __syncthreads();
    int excl = s_prefix + incl - v;
    if (i < N_NODES) { g_off[i] = excl; g_cur[i] = excl; }
    if (b == SCAN_NB - 1 && threadIdx.x == 0)
        g_off[N_NODES] = s_prefix + total;
}

__global__ void scatter_kernel(const int* __restrict__ src, const int* __restrict__ dst) {
    int i = blockIdx.x * blockDim.x + threadIdx.x;
    if (i < N_EDGES) {
        int p = atomicAdd(&g_cur[dst[i]], 1);
        g_srcs[p] = src[i];
    }
}

// pad x [N,126] fp32 -> g_fh [N,64] packed fp16
__global__ void pad_x_kernel(const float* __restrict__ x) {
    int i = blockIdx.x * blockDim.x + threadIdx.x;
    if (i < N_NODES * 64) {
        int n = i >> 6, p = i & 63;
        float2 v = make_float2(0.f, 0.f);
        if (p < 63) v = *(const float2*)&x[n * IN_DIM + 2 * p];
        __half2 h = __floats2half2_rn(v.x, v.y);
        g_fh[i] = *(uint32_t*)&h;
    }
}

__global__ void gstart_kernel(const int* __restrict__ batch) {
    int i = blockIdx.x * blockDim.x + threadIdx.x;
    if (i >= N_NODES) return;
    int b = batch[i];
    int bp = (i == 0) ? -1 : batch[i - 1];
    for (int gg = bp + 1; gg <= b; gg++) g_gstart[gg] = i;
    if (i == N_NODES - 1)
        for (int gg = b + 1; gg <= N_GRAPHS; gg++) g_gstart[gg] = N_NODES;
}

// ---------------- weight pre-split: fp32 [K,128] -> packed half2 ------------
__global__ void wsplit_kernel(const float* __restrict__ w1a, const float* __restrict__ w2a,
                              const float* __restrict__ w1b, const float* __restrict__ w2b,
                              const float* __restrict__ w1c, const float* __restrict__ w2c,
                              int Kw1) {
    int slot = blockIdx.y;
    const float* w = (slot == 0) ? w1a : (slot == 1) ? w2a : (slot == 2) ? w1b
                   : (slot == 3) ? w2b : (slot == 4) ? w1c : w2c;
    int Kw = (slot == 0) ? Kw1 : DIMH;
    int i = blockIdx.x * blockDim.x + threadIdx.x;
    if (i >= KPAIRS * 128) return;
    int kp = i >> 7, n = i & 127;
    int k0 = 2 * kp, k1 = k0 + 1;
    float v0 = (k0 < Kw) ? w[k0 * DIMH + n] : 0.0f;
    float v1 = (k1 < Kw) ? w[k1 * DIMH + n] : 0.0f;
    __half2 h = __floats2half2_rn(v0, v1);
    g_wsp[slot * KPAIRS * 128 + i] = *(uint32_t*)&h;
}

// ---------------- aggregation: warp/node, uniform index loads (no shfl) -----
__global__ __launch_bounds__(256) void agg_kernel(const uint32_t* __restrict__ F,
                                                  uint32_t* __restrict__ oh,
                                                  uint32_t* __restrict__ ol) {
    int warp = (blockIdx.x * blockDim.x + threadIdx.x) >> 5;
    int lane = threadIdx.x & 31;
    if (warp >= N_NODES) return;
    int s = g_off[warp], e = g_off[warp + 1];
    float4 acc;
    {
        uint2 v = *(const uint2*)&F[warp * KPAIRS + 2 * lane];
        float2 a = __half22float2(*(__half2*)&v.x);
        float2 b = __half22float2(*(__half2*)&v.y);
        acc = make_float4(a.x, a.y, b.x, b.y);
    }
    int j = s;
    for (; j + 4 <= e; j += 4) {
        // warp-uniform index loads (broadcast LDG, L1-resident)
        int s0 = g_srcs[j];
        int s1 = g_srcs[j + 1];
        int s2 = g_srcs[j + 2];
        int s3 = g_srcs[j + 3];
        uint2 u0 = *(const uint2*)&F[s0 * KPAIRS + 2 * lane];
        uint2 u1 = *(const uint2*)&F[s1 * KPAIRS + 2 * lane];
        uint2 u2 = *(const uint2*)&F[s2 * KPAIRS + 2 * lane];
        uint2 u3 = *(const uint2*)&F[s3 * KPAIRS + 2 * lane];
        float2 a0 = __half22float2(*(__half2*)&u0.x), b0 = __half22float2(*(__half2*)&u0.y);
        float2 a1 = __half22float2(*(__half2*)&u1.x), b1 = __half22float2(*(__half2*)&u1.y);
        float2 a2 = __half22float2(*(__half2*)&u2.x), b2 = __half22float2(*(__half2*)&u2.y);
        float2 a3 = __half22float2(*(__half2*)&u3.x), b3 = __half22float2(*(__half2*)&u3.y);
        acc.x += (a0.x + a1.x) + (a2.x + a3.x);
        acc.y += (a0.y + a1.y) + (a2.y + a3.y);
        acc.z += (b0.x + b1.x) + (b2.x + b3.x);
        acc.w += (b0.y + b1.y) + (b2.y + b3.y);
    }
    for (; j < e; j++) {
        int s0 = g_srcs[j];
        uint2 u = *(const uint2*)&F[s0 * KPAIRS + 2 * lane];
        float2 a = __half22float2(*(__half2*)&u.x), b = __half22float2(*(__half2*)&u.y);
        acc.x += a.x; acc.y += a.y; acc.z += b.x; acc.w += b.y;
    }
    __half hx = __float2half_rn(acc.x), hy = __float2half_rn(acc.y);
    __half hz = __float2half_rn(acc.z), hw = __float2half_rn(acc.w);
    __half2 h0 = __halves2half2(hx, hy), h1 = __halves2half2(hz, hw);
    __half2 l0 = __floats2half2_rn(acc.x - __half2float(hx), acc.y - __half2float(hy));
    __half2 l1 = __floats2half2_rn(acc.z - __half2float(hz), acc.w - __half2float(hw));
    uint2 hv = make_uint2(*(uint32_t*)&h0, *(uint32_t*)&h1);
    uint2 lv = make_uint2(*(uint32_t*)&l0, *(uint32_t*)&l1);
    *(uint2*)&oh[warp * KPAIRS + 2 * lane] = hv;
    *(uint2*)&ol[warp * KPAIRS + 2 * lane] = lv;
}

// ---------------- fp16 helpers ----------------
__device__ __forceinline__ uint32_t pack_f16x2(__half a, __half b) {
    __half2 p = __halves2half2(a, b);
    return *(uint32_t*)&p;
}
__device__ __forceinline__ void mma_f16(float* c, const uint32_t* a, const uint32_t* b) {
    asm volatile(
        "mma.sync.aligned.m16n8k16.row.col.f32.f16.f16.f32 "
        "{%0,%1,%2,%3}, {%4,%5,%6,%7}, {%8,%9}, {%0,%1,%2,%3};\n"
        : "+f"(c[0]), "+f"(c[1]), "+f"(c[2]), "+f"(c[3])
        : "r"(a[0]), "r"(a[1]), "r"(a[2]), "r"(a[3]), "r"(b[0]), "r"(b[1]));
}

// ---------------- fused double-GEMM per GIN layer, 64-row tile, fp16 --------
#define AST 20
#define BST 136
#define HST 68
#define SM_AH 0
#define SM_AL (64 * AST)
#define SM_B  (2 * 64 * AST)
#define SM_HH (SM_B + 16 * BST)
#define SM_HL (SM_HH + 64 * HST)
#define SMEM_U32 (SM_HH + 2 * 64 * HST)

__global__ __launch_bounds__(256, 3) void layer_gemm_kernel(
    const uint32_t* __restrict__ Ahg, const uint32_t* __restrict__ Alg,
    const uint32_t* __restrict__ W1p, const float* __restrict__ b1,
    const float* __restrict__ gamma, const float* __restrict__ beta,
    const float* __restrict__ mean, const float* __restrict__ var,
    const uint32_t* __restrict__ W2p, const float* __restrict__ b2,
    uint32_t* __restrict__ OUT16)
{
    extern __shared__ uint32_t sm[];
    uint32_t* Ah = sm + SM_AH;
    uint32_t* Al = sm + SM_AL;
    uint32_t* B  = sm + SM_B;
    uint32_t* Hh = sm + SM_HH;
    uint32_t* Hl = sm + SM_HL;

    const int tid  = threadIdx.x;
    const int wid  = tid >> 5;
    const int lane = tid & 31;
    const int g    = lane >> 2;
    const int tig  = lane & 3;
    const int wm   = wid & 1;
    const int wn   = wid >> 1;
    const int row0 = blockIdx.x * 64;

    float acc[2][4][4];

    // =========== GEMM1 ===========
    #pragma unroll
    for (int mi = 0; mi < 2; mi++)
        #pragma unroll
        for (int ni = 0; ni < 4; ni++)
            #pragma unroll
            for (int r = 0; r < 4; r++) acc[mi][ni][r] = 0.0f;

    for (int c = 0; c < 4; c++) {
        {
            int r = tid >> 2, kp4 = (tid & 3) * 4;
            int gr = row0 + r;
            uint4 vh = make_uint4(0, 0, 0, 0), vl = make_uint4(0, 0, 0, 0);
            if (gr < N_NODES) {
                vh = *(const uint4*)&Ahg[gr * KPAIRS + c * 16 + kp4];
                vl = *(const uint4*)&Alg[gr * KPAIRS + c * 16 + kp4];
            }
            *(uint4*)&Ah[r * AST + kp4] = vh;
            *(uint4*)&Al[r * AST + kp4] = vl;
        }
        #pragma unroll
        for (int l = 0; l < 2; l++) {
            int idx = tid + l * 256;
            int kp = idx >> 5;
            int c4 = (idx & 31) * 4;
            uint4 v = *(const uint4*)&W1p[(c * 16 + kp) * 128 + c4];
            *(uint4*)&B[kp * BST + c4] = v;
        }
        __syncthreads();

        #pragma unroll
        for (int ks = 0; ks < 2; ks++) {
            const int kk2 = ks * 8;
            uint32_t a_hi[2][4], a_lo[2][4];
            #pragma unroll
            for (int mi = 0; mi < 2; mi++) {
                int rm = wm * 32 + mi * 16;
                a_hi[mi][0] = Ah[(rm + g    ) * AST + kk2 + tig    ];
                a_hi[mi][1] = Ah[(rm + g + 8) * AST + kk2 + tig    ];
                a_hi[mi][2] = Ah[(rm + g    ) * AST + kk2 + tig + 4];
                a_hi[mi][3] = Ah[(rm + g + 8) * AST + kk2 + tig + 4];
                a_lo[mi][0] = Al[(rm + g    ) * AST + kk2 + tig    ];
                a_lo[mi][1] = Al[(rm + g + 8) * AST + kk2 + tig    ];
                a_lo[mi][2] = Al[(rm + g    ) * AST + kk2 + tig + 4];
                a_lo[mi][3] = Al[(rm + g + 8) * AST + kk2 + tig + 4];
            }
            #pragma unroll
            for (int ni = 0; ni < 4; ni++) {
                int cn = wn * 32 + ni * 8;
                uint32_t b[2];
                b[0] = B[(kk2 + tig    ) * BST + cn + g];
                b[1] = B[(kk2 + tig + 4) * BST + cn + g];
                #pragma unroll
                for (int mi = 0; mi < 2; mi++) {
                    mma_f16(acc[mi][ni], a_hi[mi], b);
                    mma_f16(acc[mi][ni], a_lo[mi], b);
                }
            }
        }
        __syncthreads();
    }

    // ---- epilogue1: BN+ReLU, split hi/lo -> Hh/Hl ----
    {
        float sc[4][2], sh[4][2];
        #pragma unroll
        for (int ni = 0; ni < 4; ni++) {
            #pragma unroll
            for (int j = 0; j < 2; j++) {
                int col = wn * 32 + ni * 8 + 2 * tig + j;
                float s = gamma[col] * rsqrtf(var[col] + BN_EPS);
                sc[ni][j] = s;
                sh[ni][j] = beta[col] - mean[col] * s + b1[col] * s;
            }
        }
        #pragma unroll
        for (int mi = 0; mi < 2; mi++) {
            int r0 = wm * 32 + mi * 16 + g;
            int r1 = r0 + 8;
            #pragma unroll
            for (int ni = 0; ni < 4; ni++) {
                int kp = wn * 16 + ni * 4 + tig;
                float o00 = fmaxf(acc[mi][ni][0] * sc[ni][0] + sh[ni][0], 0.0f);
                float o01 = fmaxf(acc[mi][ni][1] * sc[ni][1] + sh[ni][1], 0.0f);
                float o10 = fmaxf(acc[mi][ni][2] * sc[ni][0] + sh[ni][0], 0.0f);
                float o11 = fmaxf(acc[mi][ni][3] * sc[ni][1] + sh[ni][1], 0.0f);
                __half h00 = __float2half_rn(o00), h01 = __float2half_rn(o01);
                __half h10 = __float2half_rn(o10), h11 = __float2half_rn(o11);
                __half2 l0 = __floats2half2_rn(o00 - __half2float(h00),
                                               o01 - __half2float(h01));
                __half2 l1 = __floats2half2_rn(o10 - __half2float(h10),
                                               o11 - __half2float(h11));
                Hh[r0 * HST + kp] = pack_f16x2(h00, h01);
                Hl[r0 * HST + kp] = *(uint32_t*)&l0;
                Hh[r1 * HST + kp] = pack_f16x2(h10, h11);
                Hl[r1 * HST + kp] = *(uint32_t*)&l1;
            }
        }
    }

    // =========== GEMM2 ===========
    #pragma unroll
    for (int mi = 0; mi < 2; mi++)
        #pragma unroll
        for (int ni = 0; ni < 4; ni++)
            #pragma unroll
            for (int r = 0; r < 4; r++) acc[mi][ni][r] = 0.0f;

    for (int c = 0; c < 4; c++) {
        __syncthreads();
        #pragma unroll
        for (int l = 0; l < 2; l++) {
            int idx = tid + l * 256;
            int kp = idx >> 5;
            int c4 = (idx & 31) * 4;
            uint4 v = *(const uint4*)&W2p[(c * 16 + kp) * 128 + c4];
            *(uint4*)&B[kp * BST + c4] = v;
        }
        __syncthreads();

        #pragma unroll
        for (int ks = 0; ks < 2; ks++) {
            const int kp0 = c * 16 + ks * 8;
            uint32_t a_hi[2][4], a_lo[2][4];
            #pragma unroll
            for (int mi = 0; mi < 2; mi++) {
                int rm = wm * 32 + mi * 16;
                a_hi[mi][0] = Hh[(rm + g    ) * HST + kp0 + tig    ];
                a_hi[mi][1] = Hh[(rm + g + 8) * HST + kp0 + tig    ];
                a_hi[mi][2] = Hh[(rm + g    ) * HST + kp0 + tig + 4];
                a_hi[mi][3] = Hh[(rm + g + 8) * HST + kp0 + tig + 4];
                a_lo[mi][0] = Hl[(rm + g    ) * HST + kp0 + tig    ];
                a_lo[mi][1] = Hl[(rm + g + 8) * HST + kp0 + tig    ];
                a_lo[mi][2] = Hl[(rm + g    ) * HST + kp0 + tig + 4];
                a_lo[mi][3] = Hl[(rm + g + 8) * HST + kp0 + tig + 4];
            }
            const int kb = ks * 8;
            #pragma unroll
            for (int ni = 0; ni < 4; ni++) {
                int cn = wn * 32 + ni * 8;
                uint32_t b[2];
                b[0] = B[(kb + tig    ) * BST + cn + g];
                b[1] = B[(kb + tig + 4) * BST + cn + g];
                #pragma unroll
                for (int mi = 0; mi < 2; mi++) {
                    mma_f16(acc[mi][ni], a_hi[mi], b);
                    mma_f16(acc[mi][ni], a_lo[mi], b);
                }
            }
        }
    }

    // ---- epilogue2: bias + ReLU -> packed fp16 OUT ----
    float bb[4][2];
    #pragma unroll
    for (int ni = 0; ni < 4; ni++) {
        #pragma unroll
        for (int j = 0; j < 2; j++)
            bb[ni][j] = b2[wn * 32 + ni * 8 + 2 * tig + j];
    }
    #pragma unroll
    for (int mi = 0; mi < 2; mi++) {
        int r0 = row0 + wm * 32 + mi * 16 + g;
        int r1 = r0 + 8;
        #pragma unroll
        for (int ni = 0; ni < 4; ni++) {
            int c0 = wn * 32 + ni * 8 + 2 * tig;   // even
            int kp = c0 >> 1;
            if (r0 < N_NODES) {
                __half2 o = __floats2half2_rn(
                    fmaxf(acc[mi][ni][0] + bb[ni][0], 0.0f),
                    fmaxf(acc[mi][ni][1] + bb[ni][1], 0.0f));
                OUT16[r0 * KPAIRS + kp] = *(uint32_t*)&o;
            }
            if (r1 < N_NODES) {
                __half2 o = __floats2half2_rn(
                    fmaxf(acc[mi][ni][2] + bb[ni][0], 0.0f),
                    fmaxf(acc[mi][ni][3] + bb[ni][1], 0.0f));
                OUT16[r1 * KPAIRS + kp] = *(uint32_t*)&o;
            }
        }
    }
}

// ---------------- segment pooling over fp16 features ------------------------
__global__ void pool_seg_kernel(const uint32_t* __restrict__ h, float* __restrict__ pool) {
    int gph = blockIdx.x;
    int t = threadIdx.x;       // 0..127 -> feature t
    int u = t >> 1, hi = t & 1;
    int s = g_gstart[gph], e = g_gstart[gph + 1];
    float a0 = 0.f, a1 = 0.f;
    int r = s;
    for (; r + 2 <= e; r += 2) {
        uint32_t v0 = h[r * KPAIRS + u];
        uint32_t v1 = h[(r + 1) * KPAIRS + u];
        float2 f0 = __half22float2(*(__half2*)&v0);
        float2 f1 = __half22float2(*(__half2*)&v1);
        a0 += hi ? f0.y : f0.x;
        a1 += hi ? f1.y : f1.x;
    }
    if (r < e) {
        uint32_t v = h[r * KPAIRS + u];
        float2 f = __half22float2(*(__half2*)&v);
        a0 += hi ? f.y : f.x;
    }
    pool[gph * DIMH + t] = a0 + a1;
}

// ---------------- head ----------------
__global__ void head_kernel(const float* __restrict__ pool,
                            const float* __restrict__ l1w, const float* __restrict__ l1b,
                            const float* __restrict__ l2w, const float* __restrict__ l2b,
                            float* __restrict__ out) {
    __shared__ float hg[DIMH];
    __shared__ float o1[LIN1_DIM];
    int gph = blockIdx.x;
    int t = threadIdx.x;  // 128
    hg[t] = pool[gph * DIMH + t];
    __syncthreads();
    if (t < LIN1_DIM) {
        float s = l1b[t];
        #pragma unroll 8
        for (int k = 0; k < DIMH; k++) s += hg[k] * l1w[k * LIN1_DIM + t];
        o1[t] = fmaxf(s, 0.0f);
    }
    __syncthreads();
    if (t == 0) {
        float s = l2b[0];
        #pragma unroll 8
        for (int j = 0; j < LIN1_DIM; j++) s += o1[j] * l2w[j];
        out[gph] = 1.0f / (1.0f + expf(-s));
    }
}

// ---------------- launch ----------------
extern "C" void kernel_launch(void* const* d_in, const int* in_sizes, int n_in,
                              void* d_out, int out_size) {
    const float* x          = (const float*)d_in[0];
    const int*   edge_index = (const int*)d_in[1];
    const int*   batch      = (const int*)d_in[2];
    const float* w[3][7];
    const float* b2[3];
    for (int l = 0; l < 3; l++) {
        int base = 3 + l * 8;
        w[l][0] = (const float*)d_in[base + 0];
        w[l][1] = (const float*)d_in[base + 1];
        w[l][2] = (const float*)d_in[base + 2];
        w[l][3] = (const float*)d_in[base + 3];
        w[l][4] = (const float*)d_in[base + 4];
        w[l][5] = (const float*)d_in[base + 5];
        w[l][6] = (const float*)d_in[base + 6];
        b2[l]   = (const float*)d_in[base + 7];
    }
    const float* l1w = (const float*)d_in[27];
    const float* l1b = (const float*)d_in[28];
    const float* l2w = (const float*)d_in[29];
    const float* l2b = (const float*)d_in[30];
    float* out = (float*)d_out;

    const int* e_src = edge_index;
    const int* e_dst = edge_index + N_EDGES;

    static uint32_t* p_fh   = nullptr;
    static uint32_t* p_ah   = nullptr;
    static uint32_t* p_al   = nullptr;
    static uint32_t* p_wsp  = nullptr;
    static int*      p_cnt  = nullptr;
    static float*    p_pool = nullptr;
    if (!p_fh) {
        cudaGetSymbolAddress((void**)&p_fh,   g_fh);
        cudaGetSymbolAddress((void**)&p_ah,   g_ah);
        cudaGetSymbolAddress((void**)&p_al,   g_al);
        cudaGetSymbolAddress((void**)&p_wsp,  g_wsp);
        cudaGetSymbolAddress((void**)&p_cnt,  g_cnt);
        cudaGetSymbolAddress((void**)&p_pool, g_pool);
        cudaFuncSetAttribute(layer_gemm_kernel,
                             cudaFuncAttributeMaxDynamicSharedMemorySize,
                             SMEM_U32 * 4);
    }

    // ---- CSR build ----
    cudaMemsetAsync(p_cnt, 0, (N_NODES + 64) * sizeof(int));
    count_kernel<<<(N_EDGES + 255) / 256, 256>>>(e_dst);
    scan_onepass_kernel<<<SCAN_NB, 1024>>>();
    scatter_kernel<<<(N_EDGES + 255) / 256, 256>>>(e_src, e_dst);

    // ---- pad x, graph boundaries, weight pre-split ----
    pad_x_kernel<<<(N_NODES * 64 + 255) / 256, 256>>>(x);
    gstart_kernel<<<(N_NODES + 255) / 256, 256>>>(batch);
    {
        dim3 grid((KPAIRS * 128 + 255) / 256, 6);
        wsplit_kernel<<<grid, 256>>>(w[0][0], w[0][6], w[1][0], w[1][6],
                                     w[2][0], w[2][6], IN_DIM);
    }

    const int GEMM_GRID = (N_NODES + 63) / 64;
    const int AGG_GRID  = (N_NODES * 32 + 255) / 256;
    const size_t SMEM   = SMEM_U32 * 4;

    // ---- 3 GIN layers ----
    for (int l = 0; l < 3; l++) {
        agg_kernel<<<AGG_GRID, 256>>>(p_fh, p_ah, p_al);
        layer_gemm_kernel<<<GEMM_GRID, 256, SMEM>>>(
            p_ah, p_al,
            p_wsp + (2 * l) * KPAIRS * 128, w[l][1], w[l][2], w[l][3],
            w[l][4], w[l][5],
            p_wsp + (2 * l + 1) * KPAIRS * 128, b2[l],
            p_fh);
    }

    // ---- pool + head ----
    pool_seg_kernel<<<N_GRAPHS, 128>>>(p_fh, p_pool);
    head_kernel<<<N_GRAPHS, 128>>>(p_pool, l1w, l1b, l2w, l2b, out);
}

// round 15
// speedup vs baseline: 1.3092x; 1.1961x over previous
#include <cuda_runtime.h>
#include <cuda_fp16.h>
#include <math.h>
#include <stdint.h>

#define N_NODES 50000
#define N_EDGES 800000
#define N_GRAPHS 512
#define IN_DIM 126
#define DIMH 128
#define LIN1_DIM 64
#define BN_EPS 1e-5f

#define SCAN_NB 49   // ceil(50000/1024)
#define KPAIRS 64    // 128 k / 2 per u32

// ---------------- device scratch ----------------
__device__ uint32_t g_fh[N_NODES * KPAIRS];    // features, packed fp16 (half2)
__device__ uint32_t g_ah[N_NODES * KPAIRS];    // agg output, packed fp16
__device__ uint32_t g_wsp[6 * KPAIRS * 128];   // pre-split fp16 weights, slot-major
__device__ int      g_cnt[N_NODES + 64];       // counts + 64 tail flags
__device__ int      g_bval[64];                // block totals (flag-protected)
__device__ int      g_off[N_NODES + 1];
__device__ int      g_cur[N_NODES];
__device__ int      g_srcs[N_EDGES];
__device__ float    g_pool[N_GRAPHS * DIMH];
__device__ int      g_gstart[N_GRAPHS + 1];

// ---------------- CSR build ----------------
__global__ void count_kernel(const int* __restrict__ dst) {
    int i = blockIdx.x * blockDim.x + threadIdx.x;
    if (i < N_EDGES) atomicAdd(&g_cnt[dst[i]], 1);
}

// single-pass exclusive scan (49 blocks x 1024, all resident -> safe lookback)
__global__ void scan_onepass_kernel() {
    __shared__ int ws[32];
    __shared__ int s_prefix;
    const int b = blockIdx.x;
    int i = b * 1024 + threadIdx.x;
    int lane = threadIdx.x & 31, wid = threadIdx.x >> 5;
    int v = (i < N_NODES) ? g_cnt[i] : 0;
    int x = v;
    #pragma unroll
    for (int o = 1; o < 32; o <<= 1) {
        int t = __shfl_up_sync(0xFFFFFFFFu, x, o);
        if (lane >= o) x += t;
    }
    if (lane == 31) ws[wid] = x;
    __syncthreads();
    if (wid == 0) {
        int s = ws[lane];
        #pragma unroll
        for (int o = 1; o < 32; o <<= 1) {
            int t = __shfl_up_sync(0xFFFFFFFFu, s, o);
            if (lane >= o) s += t;
        }
        ws[lane] = s;
    }
    __syncthreads();
    int incl  = x + (wid > 0 ? ws[wid - 1] : 0);
    int total = ws[31];

    if (threadIdx.x == 0) {
        g_bval[b] = total;
        __threadfence();
        atomicExch(&g_cnt[N_NODES + b], 1);
        s_prefix = 0;
    }
    __syncthreads();
    if (threadIdx.x < b) {
        while (atomicAdd(&g_cnt[N_NODES + threadIdx.x], 0) == 0) { }
        atomicAdd(&s_prefix, g_bval[threadIdx.x]);
    }
    __syncthreads();
    int excl = s_prefix + incl - v;
    if (i < N_NODES) { g_off[i] = excl; g_cur[i] = excl; }
    if (b == SCAN_NB - 1 && threadIdx.x == 0)
        g_off[N_NODES] = s_prefix + total;
}

__global__ void scatter_kernel(const int* __restrict__ src, const int* __restrict__ dst) {
    int i = blockIdx.x * blockDim.x + threadIdx.x;
    if (i < N_EDGES) {
        int p = atomicAdd(&g_cur[dst[i]], 1);
        g_srcs[p] = src[i];
    }
}

// pad x [N,126] fp32 -> g_fh [N,64] packed fp16
__global__ void pad_x_kernel(const float* __restrict__ x) {
    int i = blockIdx.x * blockDim.x + threadIdx.x;
    if (i < N_NODES * 64) {
        int n = i >> 6, p = i & 63;
        float2 v = make_float2(0.f, 0.f);
        if (p < 63) v = *(const float2*)&x[n * IN_DIM + 2 * p];
        __half2 h = __floats2half2_rn(v.x, v.y);
        g_fh[i] = *(uint32_t*)&h;
    }
}

__global__ void gstart_kernel(const int* __restrict__ batch) {
    int i = blockIdx.x * blockDim.x + threadIdx.x;
    if (i >= N_NODES) return;
    int b = batch[i];
    int bp = (i == 0) ? -1 : batch[i - 1];
    for (int gg = bp + 1; gg <= b; gg++) g_gstart[gg] = i;
    if (i == N_NODES - 1)
        for (int gg = b + 1; gg <= N_GRAPHS; gg++) g_gstart[gg] = N_NODES;
}

// ---------------- weight pre-split: fp32 [K,128] -> packed half2 ------------
__global__ void wsplit_kernel(const float* __restrict__ w1a, const float* __restrict__ w2a,
                              const float* __restrict__ w1b, const float* __restrict__ w2b,
                              const float* __restrict__ w1c, const float* __restrict__ w2c,
                              int Kw1) {
    int slot = blockIdx.y;
    const float* w = (slot == 0) ? w1a : (slot == 1) ? w2a : (slot == 2) ? w1b
                   : (slot == 3) ? w2b : (slot == 4) ? w1c : w2c;
    int Kw = (slot == 0) ? Kw1 : DIMH;
    int i = blockIdx.x * blockDim.x + threadIdx.x;
    if (i >= KPAIRS * 128) return;
    int kp = i >> 7, n = i & 127;
    int k0 = 2 * kp, k1 = k0 + 1;
    float v0 = (k0 < Kw) ? w[k0 * DIMH + n] : 0.0f;
    float v1 = (k1 < Kw) ? w[k1 * DIMH + n] : 0.0f;
    __half2 h = __floats2half2_rn(v0, v1);
    g_wsp[slot * KPAIRS * 128 + i] = *(uint32_t*)&h;
}

// ---------------- aggregation: warp/node, uniform index loads ---------------
__global__ __launch_bounds__(256) void agg_kernel(const uint32_t* __restrict__ F,
                                                  uint32_t* __restrict__ oh) {
    int warp = (blockIdx.x * blockDim.x + threadIdx.x) >> 5;
    int lane = threadIdx.x & 31;
    if (warp >= N_NODES) return;
    int s = g_off[warp], e = g_off[warp + 1];
    float4 acc;
    {
        uint2 v = *(const uint2*)&F[warp * KPAIRS + 2 * lane];
        float2 a = __half22float2(*(__half2*)&v.x);
        float2 b = __half22float2(*(__half2*)&v.y);
        acc = make_float4(a.x, a.y, b.x, b.y);
    }
    int j = s;
    for (; j + 4 <= e; j += 4) {
        int s0 = g_srcs[j];
        int s1 = g_srcs[j + 1];
        int s2 = g_srcs[j + 2];
        int s3 = g_srcs[j + 3];
        uint2 u0 = *(const uint2*)&F[s0 * KPAIRS + 2 * lane];
        uint2 u1 = *(const uint2*)&F[s1 * KPAIRS + 2 * lane];
        uint2 u2 = *(const uint2*)&F[s2 * KPAIRS + 2 * lane];
        uint2 u3 = *(const uint2*)&F[s3 * KPAIRS + 2 * lane];
        float2 a0 = __half22float2(*(__half2*)&u0.x), b0 = __half22float2(*(__half2*)&u0.y);
        float2 a1 = __half22float2(*(__half2*)&u1.x), b1 = __half22float2(*(__half2*)&u1.y);
        float2 a2 = __half22float2(*(__half2*)&u2.x), b2 = __half22float2(*(__half2*)&u2.y);
        float2 a3 = __half22float2(*(__half2*)&u3.x), b3 = __half22float2(*(__half2*)&u3.y);
        acc.x += (a0.x + a1.x) + (a2.x + a3.x);
        acc.y += (a0.y + a1.y) + (a2.y + a3.y);
        acc.z += (b0.x + b1.x) + (b2.x + b3.x);
        acc.w += (b0.y + b1.y) + (b2.y + b3.y);
    }
    for (; j < e; j++) {
        int s0 = g_srcs[j];
        uint2 u = *(const uint2*)&F[s0 * KPAIRS + 2 * lane];
        float2 a = __half22float2(*(__half2*)&u.x), b = __half22float2(*(__half2*)&u.y);
        acc.x += a.x; acc.y += a.y; acc.z += b.x; acc.w += b.y;
    }
    __half2 h0 = __floats2half2_rn(acc.x, acc.y);
    __half2 h1 = __floats2half2_rn(acc.z, acc.w);
    uint2 hv = make_uint2(*(uint32_t*)&h0, *(uint32_t*)&h1);
    *(uint2*)&oh[warp * KPAIRS + 2 * lane] = hv;
}

// ---------------- fp16 helpers ----------------
__device__ __forceinline__ void mma_f16(float* c, const uint32_t* a, const uint32_t* b) {
    asm volatile(
        "mma.sync.aligned.m16n8k16.row.col.f32.f16.f16.f32 "
        "{%0,%1,%2,%3}, {%4,%5,%6,%7}, {%8,%9}, {%0,%1,%2,%3};\n"
        : "+f"(c[0]), "+f"(c[1]), "+f"(c[2]), "+f"(c[3])
        : "r"(a[0]), "r"(a[1]), "r"(a[2]), "r"(a[3]), "r"(b[0]), "r"(b[1]));
}

// ---------------- fused double-GEMM per GIN layer, 64-row tile, plain fp16 --
#define AST 20
#define BST 136
#define HST 68
#define SM_AH 0
#define SM_B  (64 * AST)
#define SM_HH (SM_B + 16 * BST)
#define SMEM_U32 (SM_HH + 64 * HST)

__global__ __launch_bounds__(256, 3) void layer_gemm_kernel(
    const uint32_t* __restrict__ Ahg,
    const uint32_t* __restrict__ W1p, const float* __restrict__ b1,
    const float* __restrict__ gamma, const float* __restrict__ beta,
    const float* __restrict__ mean, const float* __restrict__ var,
    const uint32_t* __restrict__ W2p, const float* __restrict__ b2,
    uint32_t* __restrict__ OUT16)
{
    extern __shared__ uint32_t sm[];
    uint32_t* Ah = sm + SM_AH;
    uint32_t* B  = sm + SM_B;
    uint32_t* Hh = sm + SM_HH;

    const int tid  = threadIdx.x;
    const int wid  = tid >> 5;
    const int lane = tid & 31;
    const int g    = lane >> 2;
    const int tig  = lane & 3;
    const int wm   = wid & 1;
    const int wn   = wid >> 1;
    const int row0 = blockIdx.x * 64;

    float acc[2][4][4];

    // =========== GEMM1 ===========
    #pragma unroll
    for (int mi = 0; mi < 2; mi++)
        #pragma unroll
        for (int ni = 0; ni < 4; ni++)
            #pragma unroll
            for (int r = 0; r < 4; r++) acc[mi][ni][r] = 0.0f;

    for (int c = 0; c < 4; c++) {
        {
            int r = tid >> 2, kp4 = (tid & 3) * 4;
            int gr = row0 + r;
            uint4 vh = make_uint4(0, 0, 0, 0);
            if (gr < N_NODES)
                vh = *(const uint4*)&Ahg[gr * KPAIRS + c * 16 + kp4];
            *(uint4*)&Ah[r * AST + kp4] = vh;
        }
        #pragma unroll
        for (int l = 0; l < 2; l++) {
            int idx = tid + l * 256;
            int kp = idx >> 5;
            int c4 = (idx & 31) * 4;
            uint4 v = *(const uint4*)&W1p[(c * 16 + kp) * 128 + c4];
            *(uint4*)&B[kp * BST + c4] = v;
        }
        __syncthreads();

        #pragma unroll
        for (int ks = 0; ks < 2; ks++) {
            const int kk2 = ks * 8;
            uint32_t a_hi[2][4];
            #pragma unroll
            for (int mi = 0; mi < 2; mi++) {
                int rm = wm * 32 + mi * 16;
                a_hi[mi][0] = Ah[(rm + g    ) * AST + kk2 + tig    ];
                a_hi[mi][1] = Ah[(rm + g + 8) * AST + kk2 + tig    ];
                a_hi[mi][2] = Ah[(rm + g    ) * AST + kk2 + tig + 4];
                a_hi[mi][3] = Ah[(rm + g + 8) * AST + kk2 + tig + 4];
            }
            #pragma unroll
            for (int ni = 0; ni < 4; ni++) {
                int cn = wn * 32 + ni * 8;
                uint32_t b[2];
                b[0] = B[(kk2 + tig    ) * BST + cn + g];
                b[1] = B[(kk2 + tig + 4) * BST + cn + g];
                #pragma unroll
                for (int mi = 0; mi < 2; mi++)
                    mma_f16(acc[mi][ni], a_hi[mi], b);
            }
        }
        __syncthreads();
    }

    // ---- epilogue1: BN+ReLU -> Hh (plain fp16) ----
    {
        float sc[4][2], sh[4][2];
        #pragma unroll
        for (int ni = 0; ni < 4; ni++) {
            #pragma unroll
            for (int j = 0; j < 2; j++) {
                int col = wn * 32 + ni * 8 + 2 * tig + j;
                float s = gamma[col] * rsqrtf(var[col] + BN_EPS);
                sc[ni][j] = s;
                sh[ni][j] = beta[col] - mean[col] * s + b1[col] * s;
            }
        }
        #pragma unroll
        for (int mi = 0; mi < 2; mi++) {
            int r0 = wm * 32 + mi * 16 + g;
            int r1 = r0 + 8;
            #pragma unroll
            for (int ni = 0; ni < 4; ni++) {
                int kp = wn * 16 + ni * 4 + tig;
                float o00 = fmaxf(acc[mi][ni][0] * sc[ni][0] + sh[ni][0], 0.0f);
                float o01 = fmaxf(acc[mi][ni][1] * sc[ni][1] + sh[ni][1], 0.0f);
                float o10 = fmaxf(acc[mi][ni][2] * sc[ni][0] + sh[ni][0], 0.0f);
                float o11 = fmaxf(acc[mi][ni][3] * sc[ni][1] + sh[ni][1], 0.0f);
                __half2 h0 = __floats2half2_rn(o00, o01);
                __half2 h1 = __floats2half2_rn(o10, o11);
                Hh[r0 * HST + kp] = *(uint32_t*)&h0;
                Hh[r1 * HST + kp] = *(uint32_t*)&h1;
            }
        }
    }

    // =========== GEMM2 ===========
    #pragma unroll
    for (int mi = 0; mi < 2; mi++)
        #pragma unroll
        for (int ni = 0; ni < 4; ni++)
            #pragma unroll
            for (int r = 0; r < 4; r++) acc[mi][ni][r] = 0.0f;

    for (int c = 0; c < 4; c++) {
        __syncthreads();   // H writes visible (c==0) / prev-chunk B reads done
        #pragma unroll
        for (int l = 0; l < 2; l++) {
            int idx = tid + l * 256;
            int kp = idx >> 5;
            int c4 = (idx & 31) * 4;
            uint4 v = *(const uint4*)&W2p[(c * 16 + kp) * 128 + c4];
            *(uint4*)&B[kp * BST + c4] = v;
        }
        __syncthreads();

        #pragma unroll
        for (int ks = 0; ks < 2; ks++) {
            const int kp0 = c * 16 + ks * 8;
            uint32_t a_hi[2][4];
            #pragma unroll
            for (int mi = 0; mi < 2; mi++) {
                int rm = wm * 32 + mi * 16;
                a_hi[mi][0] = Hh[(rm + g    ) * HST + kp0 + tig    ];
                a_hi[mi][1] = Hh[(rm + g + 8) * HST + kp0 + tig    ];
                a_hi[mi][2] = Hh[(rm + g    ) * HST + kp0 + tig + 4];
                a_hi[mi][3] = Hh[(rm + g + 8) * HST + kp0 + tig + 4];
            }
            const int kb = ks * 8;
            #pragma unroll
            for (int ni = 0; ni < 4; ni++) {
                int cn = wn * 32 + ni * 8;
                uint32_t b[2];
                b[0] = B[(kb + tig    ) * BST + cn + g];
                b[1] = B[(kb + tig + 4) * BST + cn + g];
                #pragma unroll
                for (int mi = 0; mi < 2; mi++)
                    mma_f16(acc[mi][ni], a_hi[mi], b);
            }
        }
    }

    // ---- epilogue2: bias + ReLU -> packed fp16 OUT ----
    float bb[4][2];
    #pragma unroll
    for (int ni = 0; ni < 4; ni++) {
        #pragma unroll
        for (int j = 0; j < 2; j++)
            bb[ni][j] = b2[wn * 32 + ni * 8 + 2 * tig + j];
    }
    #pragma unroll
    for (int mi = 0; mi < 2; mi++) {
        int r0 = row0 + wm * 32 + mi * 16 + g;
        int r1 = r0 + 8;
        #pragma unroll
        for (int ni = 0; ni < 4; ni++) {
            int c0 = wn * 32 + ni * 8 + 2 * tig;   // even
            int kp = c0 >> 1;
            if (r0 < N_NODES) {
                __half2 o = __floats2half2_rn(
                    fmaxf(acc[mi][ni][0] + bb[ni][0], 0.0f),
                    fmaxf(acc[mi][ni][1] + bb[ni][1], 0.0f));
                OUT16[r0 * KPAIRS + kp] = *(uint32_t*)&o;
            }
            if (r1 < N_NODES) {
                __half2 o = __floats2half2_rn(
                    fmaxf(acc[mi][ni][2] + bb[ni][0], 0.0f),
                    fmaxf(acc[mi][ni][3] + bb[ni][1], 0.0f));
                OUT16[r1 * KPAIRS + kp] = *(uint32_t*)&o;
            }
        }
    }
}

// ---------------- segment pooling over fp16 features ------------------------
__global__ void pool_seg_kernel(const uint32_t* __restrict__ h, float* __restrict__ pool) {
    int gph = blockIdx.x;
    int t = threadIdx.x;       // 0..127 -> feature t
    int u = t >> 1, hi = t & 1;
    int s = g_gstart[gph], e = g_gstart[gph + 1];
    float a0 = 0.f, a1 = 0.f;
    int r = s;
    for (; r + 2 <= e; r += 2) {
        uint32_t v0 = h[r * KPAIRS + u];
        uint32_t v1 = h[(r + 1) * KPAIRS + u];
        float2 f0 = __half22float2(*(__half2*)&v0);
        float2 f1 = __half22float2(*(__half2*)&v1);
        a0 += hi ? f0.y : f0.x;
        a1 += hi ? f1.y : f1.x;
    }
    if (r < e) {
        uint32_t v = h[r * KPAIRS + u];
        float2 f = __half22float2(*(__half2*)&v);
        a0 += hi ? f.y : f.x;
    }
    pool[gph * DIMH + t] = a0 + a1;
}

// ---------------- head ----------------
__global__ void head_kernel(const float* __restrict__ pool,
                            const float* __restrict__ l1w, const float* __restrict__ l1b,
                            const float* __restrict__ l2w, const float* __restrict__ l2b,
                            float* __restrict__ out) {
    __shared__ float hg[DIMH];
    __shared__ float o1[LIN1_DIM];
    int gph = blockIdx.x;
    int t = threadIdx.x;  // 128
    hg[t] = pool[gph * DIMH + t];
    __syncthreads();
    if (t < LIN1_DIM) {
        float s = l1b[t];
        #pragma unroll 8
        for (int k = 0; k < DIMH; k++) s += hg[k] * l1w[k * LIN1_DIM + t];
        o1[t] = fmaxf(s, 0.0f);
    }
    __syncthreads();
    if (t == 0) {
        float s = l2b[0];
        #pragma unroll 8
        for (int j = 0; j < LIN1_DIM; j++) s += o1[j] * l2w[j];
        out[gph] = 1.0f / (1.0f + expf(-s));
    }
}

// ---------------- launch ----------------
extern "C" void kernel_launch(void* const* d_in, const int* in_sizes, int n_in,
                              void* d_out, int out_size) {
    const float* x          = (const float*)d_in[0];
    const int*   edge_index = (const int*)d_in[1];
    const int*   batch      = (const int*)d_in[2];
    const float* w[3][7];
    const float* b2[3];
    for (int l = 0; l < 3; l++) {
        int base = 3 + l * 8;
        w[l][0] = (const float*)d_in[base + 0];
        w[l][1] = (const float*)d_in[base + 1];
        w[l][2] = (const float*)d_in[base + 2];
        w[l][3] = (const float*)d_in[base + 3];
        w[l][4] = (const float*)d_in[base + 4];
        w[l][5] = (const float*)d_in[base + 5];
        w[l][6] = (const float*)d_in[base + 6];
        b2[l]   = (const float*)d_in[base + 7];
    }
    const float* l1w = (const float*)d_in[27];
    const float* l1b = (const float*)d_in[28];
    const float* l2w = (const float*)d_in[29];
    const float* l2b = (const float*)d_in[30];
    float* out = (float*)d_out;

    const int* e_src = edge_index;
    const int* e_dst = edge_index + N_EDGES;

    static uint32_t* p_fh   = nullptr;
    static uint32_t* p_ah   = nullptr;
    static uint32_t* p_wsp  = nullptr;
    static int*      p_cnt  = nullptr;
    static float*    p_pool = nullptr;
    if (!p_fh) {
        cudaGetSymbolAddress((void**)&p_fh,   g_fh);
        cudaGetSymbolAddress((void**)&p_ah,   g_ah);
        cudaGetSymbolAddress((void**)&p_wsp,  g_wsp);
        cudaGetSymbolAddress((void**)&p_cnt,  g_cnt);
        cudaGetSymbolAddress((void**)&p_pool, g_pool);
        cudaFuncSetAttribute(layer_gemm_kernel,
                             cudaFuncAttributeMaxDynamicSharedMemorySize,
                             SMEM_U32 * 4);
    }

    // ---- CSR build ----
    cudaMemsetAsync(p_cnt, 0, (N_NODES + 64) * sizeof(int));
    count_kernel<<<(N_EDGES + 255) / 256, 256>>>(e_dst);
    scan_onepass_kernel<<<SCAN_NB, 1024>>>();
    scatter_kernel<<<(N_EDGES + 255) / 256, 256>>>(e_src, e_dst);

    // ---- pad x, graph boundaries, weight pre-split ----
    pad_x_kernel<<<(N_NODES * 64 + 255) / 256, 256>>>(x);
    gstart_kernel<<<(N_NODES + 255) / 256, 256>>>(batch);
    {
        dim3 grid((KPAIRS * 128 + 255) / 256, 6);
        wsplit_kernel<<<grid, 256>>>(w[0][0], w[0][6], w[1][0], w[1][6],
                                     w[2][0], w[2][6], IN_DIM);
    }

    const int GEMM_GRID = (N_NODES + 63) / 64;
    const int AGG_GRID  = (N_NODES * 32 + 255) / 256;
    const size_t SMEM   = SMEM_U32 * 4;

    // ---- 3 GIN layers ----
    for (int l = 0; l < 3; l++) {
        agg_kernel<<<AGG_GRID, 256>>>(p_fh, p_ah);
        layer_gemm_kernel<<<GEMM_GRID, 256, SMEM>>>(
            p_ah,
            p_wsp + (2 * l) * KPAIRS * 128, w[l][1], w[l][2], w[l][3],
            w[l][4], w[l][5],
            p_wsp + (2 * l + 1) * KPAIRS * 128, b2[l],
            p_fh);
    }

    // ---- pool + head ----
    pool_seg_kernel<<<N_GRAPHS, 128>>>(p_fh, p_pool);
    head_kernel<<<N_GRAPHS, 128>>>(p_pool, l1w, l1b, l2w, l2b, out);
}

// round 16
// speedup vs baseline: 1.3315x; 1.0171x over previous
#include <cuda_runtime.h>
#include <cuda_fp16.h>
#include <math.h>
#include <stdint.h>

#define N_NODES 50000
#define N_EDGES 800000
#define N_GRAPHS 512
#define IN_DIM 126
#define DIMH 128
#define LIN1_DIM 64
#define BN_EPS 1e-5f

#define SCAN_NB 49   // ceil(50000/1024)
#define KPAIRS 64    // 128 k / 2 per u32

// ---------------- device scratch ----------------
__device__ uint32_t g_fh[N_NODES * KPAIRS];    // features, packed fp16 (half2)
__device__ uint32_t g_ah[N_NODES * KPAIRS];    // agg output, packed fp16
__device__ uint32_t g_wsp[6 * KPAIRS * 128];   // pre-split fp16 weights, slot-major
__device__ int      g_cnt[N_NODES + 64];       // counts + 64 tail flags
__device__ int      g_bval[64];                // block totals (flag-protected)
__device__ int      g_off[N_NODES + 1];
__device__ int      g_cur[N_NODES];
__device__ int      g_srcs[N_EDGES];
__device__ int      g_gstart[N_GRAPHS + 1];

// ---------------- CSR build ----------------
__global__ void count_kernel(const int* __restrict__ dst) {
    int i = blockIdx.x * blockDim.x + threadIdx.x;
    if (i < N_EDGES) atomicAdd(&g_cnt[dst[i]], 1);
}

// single-pass exclusive scan (49 blocks x 1024, all resident -> safe lookback)
__global__ void scan_onepass_kernel() {
    __shared__ int ws[32];
    __shared__ int s_prefix;
    const int b = blockIdx.x;
    int i = b * 1024 + threadIdx.x;
    int lane = threadIdx.x & 31, wid = threadIdx.x >> 5;
    int v = (i < N_NODES) ? g_cnt[i] : 0;
    int x = v;
    #pragma unroll
    for (int o = 1; o < 32; o <<= 1) {
        int t = __shfl_up_sync(0xFFFFFFFFu, x, o);
        if (lane >= o) x += t;
    }
    if (lane == 31) ws[wid] = x;
    __syncthreads();
    if (wid == 0) {
        int s = ws[lane];
        #pragma unroll
        for (int o = 1; o < 32; o <<= 1) {
            int t = __shfl_up_sync(0xFFFFFFFFu, s, o);
            if (lane >= o) s += t;
        }
        ws[lane] = s;
    }
    __syncthreads();
    int incl  = x + (wid > 0 ? ws[wid - 1] : 0);
    int total = ws[31];

    if (threadIdx.x == 0) {
        g_bval[b] = total;
        __threadfence();
        atomicExch(&g_cnt[N_NODES + b], 1);
        s_prefix = 0;
    }
    __syncthreads();
    if (threadIdx.x < b) {
        while (atomicAdd(&g_cnt[N_NODES + threadIdx.x], 0) == 0) { }
        atomicAdd(&s_prefix, g_bval[threadIdx.x]);
    }
    __syncthreads();
    int excl = s_prefix + incl - v;
    if (i < N_NODES) { g_off[i] = excl; g_cur[i] = excl; }
    if (b == SCAN_NB - 1 && threadIdx.x == 0)
        g_off[N_NODES] = s_prefix + total;
}

__global__ void scatter_kernel(const int* __restrict__ src, const int* __restrict__ dst) {
    int i = blockIdx.x * blockDim.x + threadIdx.x;
    if (i < N_EDGES) {
        int p = atomicAdd(&g_cur[dst[i]], 1);
        g_srcs[p] = src[i];
    }
}

// pad x [N,126] fp32 -> g_fh [N,64] packed fp16
__global__ void pad_x_kernel(const float* __restrict__ x) {
    int i = blockIdx.x * blockDim.x + threadIdx.x;
    if (i < N_NODES * 64) {
        int n = i >> 6, p = i & 63;
        float2 v = make_float2(0.f, 0.f);
        if (p < 63) v = *(const float2*)&x[n * IN_DIM + 2 * p];
        __half2 h = __floats2half2_rn(v.x, v.y);
        g_fh[i] = *(uint32_t*)&h;
    }
}

__global__ void gstart_kernel(const int* __restrict__ batch) {
    int i = blockIdx.x * blockDim.x + threadIdx.x;
    if (i >= N_NODES) return;
    int b = batch[i];
    int bp = (i == 0) ? -1 : batch[i - 1];
    for (int gg = bp + 1; gg <= b; gg++) g_gstart[gg] = i;
    if (i == N_NODES - 1)
        for (int gg = b + 1; gg <= N_GRAPHS; gg++) g_gstart[gg] = N_NODES;
}

// ---------------- weight pre-split: fp32 [K,128] -> packed half2 ------------
__global__ void wsplit_kernel(const float* __restrict__ w1a, const float* __restrict__ w2a,
                              const float* __restrict__ w1b, const float* __restrict__ w2b,
                              const float* __restrict__ w1c, const float* __restrict__ w2c,
                              int Kw1) {
    int slot = blockIdx.y;
    const float* w = (slot == 0) ? w1a : (slot == 1) ? w2a : (slot == 2) ? w1b
                   : (slot == 3) ? w2b : (slot == 4) ? w1c : w2c;
    int Kw = (slot == 0) ? Kw1 : DIMH;
    int i = blockIdx.x * blockDim.x + threadIdx.x;
    if (i >= KPAIRS * 128) return;
    int kp = i >> 7, n = i & 127;
    int k0 = 2 * kp, k1 = k0 + 1;
    float v0 = (k0 < Kw) ? w[k0 * DIMH + n] : 0.0f;
    float v1 = (k1 < Kw) ? w[k1 * DIMH + n] : 0.0f;
    __half2 h = __floats2half2_rn(v0, v1);
    g_wsp[slot * KPAIRS * 128 + i] = *(uint32_t*)&h;
}

// ---------------- aggregation: warp/node, uniform index loads ---------------
__global__ __launch_bounds__(256) void agg_kernel(const uint32_t* __restrict__ F,
                                                  uint32_t* __restrict__ oh) {
    int warp = (blockIdx.x * blockDim.x + threadIdx.x) >> 5;
    int lane = threadIdx.x & 31;
    if (warp >= N_NODES) return;
    int s = g_off[warp], e = g_off[warp + 1];
    float4 acc;
    {
        uint2 v = *(const uint2*)&F[warp * KPAIRS + 2 * lane];
        float2 a = __half22float2(*(__half2*)&v.x);
        float2 b = __half22float2(*(__half2*)&v.y);
        acc = make_float4(a.x, a.y, b.x, b.y);
    }
    int j = s;
    for (; j + 4 <= e; j += 4) {
        int s0 = g_srcs[j];
        int s1 = g_srcs[j + 1];
        int s2 = g_srcs[j + 2];
        int s3 = g_srcs[j + 3];
        uint2 u0 = *(const uint2*)&F[s0 * KPAIRS + 2 * lane];
        uint2 u1 = *(const uint2*)&F[s1 * KPAIRS + 2 * lane];
        uint2 u2 = *(const uint2*)&F[s2 * KPAIRS + 2 * lane];
        uint2 u3 = *(const uint2*)&F[s3 * KPAIRS + 2 * lane];
        float2 a0 = __half22float2(*(__half2*)&u0.x), b0 = __half22float2(*(__half2*)&u0.y);
        float2 a1 = __half22float2(*(__half2*)&u1.x), b1 = __half22float2(*(__half2*)&u1.y);
        float2 a2 = __half22float2(*(__half2*)&u2.x), b2 = __half22float2(*(__half2*)&u2.y);
        float2 a3 = __half22float2(*(__half2*)&u3.x), b3 = __half22float2(*(__half2*)&u3.y);
        acc.x += (a0.x + a1.x) + (a2.x + a3.x);
        acc.y += (a0.y + a1.y) + (a2.y + a3.y);
        acc.z += (b0.x + b1.x) + (b2.x + b3.x);
        acc.w += (b0.y + b1.y) + (b2.y + b3.y);
    }
    for (; j < e; j++) {
        int s0 = g_srcs[j];
        uint2 u = *(const uint2*)&F[s0 * KPAIRS + 2 * lane];
        float2 a = __half22float2(*(__half2*)&u.x), b = __half22float2(*(__half2*)&u.y);
        acc.x += a.x; acc.y += a.y; acc.z += b.x; acc.w += b.y;
    }
    __half2 h0 = __floats2half2_rn(acc.x, acc.y);
    __half2 h1 = __floats2half2_rn(acc.z, acc.w);
    uint2 hv = make_uint2(*(uint32_t*)&h0, *(uint32_t*)&h1);
    *(uint2*)&oh[warp * KPAIRS + 2 * lane] = hv;
}

// ---------------- fp16 helpers ----------------
__device__ __forceinline__ void mma_f16(float* c, const uint32_t* a, const uint32_t* b) {
    asm volatile(
        "mma.sync.aligned.m16n8k16.row.col.f32.f16.f16.f32 "
        "{%0,%1,%2,%3}, {%4,%5,%6,%7}, {%8,%9}, {%0,%1,%2,%3};\n"
        : "+f"(c[0]), "+f"(c[1]), "+f"(c[2]), "+f"(c[3])
        : "r"(a[0]), "r"(a[1]), "r"(a[2]), "r"(a[3]), "r"(b[0]), "r"(b[1]));
}

// ---------------- fused double-GEMM per GIN layer, 64-row tile, plain fp16 --
#define AST 20
#define BST 136
#define HST 68
#define SM_AH 0
#define SM_B  (64 * AST)
#define SM_HH (SM_B + 16 * BST)
#define SMEM_U32 (SM_HH + 64 * HST)

__global__ __launch_bounds__(256, 3) void layer_gemm_kernel(
    const uint32_t* __restrict__ Ahg,
    const uint32_t* __restrict__ W1p, const float* __restrict__ b1,
    const float* __restrict__ gamma, const float* __restrict__ beta,
    const float* __restrict__ mean, const float* __restrict__ var,
    const uint32_t* __restrict__ W2p, const float* __restrict__ b2,
    uint32_t* __restrict__ OUT16)
{
    extern __shared__ uint32_t sm[];
    uint32_t* Ah = sm + SM_AH;
    uint32_t* B  = sm + SM_B;
    uint32_t* Hh = sm + SM_HH;

    const int tid  = threadIdx.x;
    const int wid  = tid >> 5;
    const int lane = tid & 31;
    const int g    = lane >> 2;
    const int tig  = lane & 3;
    const int wm   = wid & 1;
    const int wn   = wid >> 1;
    const int row0 = blockIdx.x * 64;

    float acc[2][4][4];

    // =========== GEMM1 ===========
    #pragma unroll
    for (int mi = 0; mi < 2; mi++)
        #pragma unroll
        for (int ni = 0; ni < 4; ni++)
            #pragma unroll
            for (int r = 0; r < 4; r++) acc[mi][ni][r] = 0.0f;

    for (int c = 0; c < 4; c++) {
        {
            int r = tid >> 2, kp4 = (tid & 3) * 4;
            int gr = row0 + r;
            uint4 vh = make_uint4(0, 0, 0, 0);
            if (gr < N_NODES)
                vh = *(const uint4*)&Ahg[gr * KPAIRS + c * 16 + kp4];
            *(uint4*)&Ah[r * AST + kp4] = vh;
        }
        #pragma unroll
        for (int l = 0; l < 2; l++) {
            int idx = tid + l * 256;
            int kp = idx >> 5;
            int c4 = (idx & 31) * 4;
            uint4 v = *(const uint4*)&W1p[(c * 16 + kp) * 128 + c4];
            *(uint4*)&B[kp * BST + c4] = v;
        }
        __syncthreads();

        #pragma unroll
        for (int ks = 0; ks < 2; ks++) {
            const int kk2 = ks * 8;
            uint32_t a_hi[2][4];
            #pragma unroll
            for (int mi = 0; mi < 2; mi++) {
                int rm = wm * 32 + mi * 16;
                a_hi[mi][0] = Ah[(rm + g    ) * AST + kk2 + tig    ];
                a_hi[mi][1] = Ah[(rm + g + 8) * AST + kk2 + tig    ];
                a_hi[mi][2] = Ah[(rm + g    ) * AST + kk2 + tig + 4];
                a_hi[mi][3] = Ah[(rm + g + 8) * AST + kk2 + tig + 4];
            }
            #pragma unroll
            for (int ni = 0; ni < 4; ni++) {
                int cn = wn * 32 + ni * 8;
                uint32_t b[2];
                b[0] = B[(kk2 + tig    ) * BST + cn + g];
                b[1] = B[(kk2 + tig + 4) * BST + cn + g];
                #pragma unroll
                for (int mi = 0; mi < 2; mi++)
                    mma_f16(acc[mi][ni], a_hi[mi], b);
            }
        }
        __syncthreads();
    }

    // ---- epilogue1: BN+ReLU -> Hh (plain fp16) ----
    {
        float sc[4][2], sh[4][2];
        #pragma unroll
        for (int ni = 0; ni < 4; ni++) {
            #pragma unroll
            for (int j = 0; j < 2; j++) {
                int col = wn * 32 + ni * 8 + 2 * tig + j;
                float s = gamma[col] * rsqrtf(var[col] + BN_EPS);
                sc[ni][j] = s;
                sh[ni][j] = beta[col] - mean[col] * s + b1[col] * s;
            }
        }
        #pragma unroll
        for (int mi = 0; mi < 2; mi++) {
            int r0 = wm * 32 + mi * 16 + g;
            int r1 = r0 + 8;
            #pragma unroll
            for (int ni = 0; ni < 4; ni++) {
                int kp = wn * 16 + ni * 4 + tig;
                float o00 = fmaxf(acc[mi][ni][0] * sc[ni][0] + sh[ni][0], 0.0f);
                float o01 = fmaxf(acc[mi][ni][1] * sc[ni][1] + sh[ni][1], 0.0f);
                float o10 = fmaxf(acc[mi][ni][2] * sc[ni][0] + sh[ni][0], 0.0f);
                float o11 = fmaxf(acc[mi][ni][3] * sc[ni][1] + sh[ni][1], 0.0f);
                __half2 h0 = __floats2half2_rn(o00, o01);
                __half2 h1 = __floats2half2_rn(o10, o11);
                Hh[r0 * HST + kp] = *(uint32_t*)&h0;
                Hh[r1 * HST + kp] = *(uint32_t*)&h1;
            }
        }
    }

    // =========== GEMM2 ===========
    #pragma unroll
    for (int mi = 0; mi < 2; mi++)
        #pragma unroll
        for (int ni = 0; ni < 4; ni++)
            #pragma unroll
            for (int r = 0; r < 4; r++) acc[mi][ni][r] = 0.0f;

    for (int c = 0; c < 4; c++) {
        __syncthreads();
        #pragma unroll
        for (int l = 0; l < 2; l++) {
            int idx = tid + l * 256;
            int kp = idx >> 5;
            int c4 = (idx & 31) * 4;
            uint4 v = *(const uint4*)&W2p[(c * 16 + kp) * 128 + c4];
            *(uint4*)&B[kp * BST + c4] = v;
        }
        __syncthreads();

        #pragma unroll
        for (int ks = 0; ks < 2; ks++) {
            const int kp0 = c * 16 + ks * 8;
            uint32_t a_hi[2][4];
            #pragma unroll
            for (int mi = 0; mi < 2; mi++) {
                int rm = wm * 32 + mi * 16;
                a_hi[mi][0] = Hh[(rm + g    ) * HST + kp0 + tig    ];
                a_hi[mi][1] = Hh[(rm + g + 8) * HST + kp0 + tig    ];
                a_hi[mi][2] = Hh[(rm + g    ) * HST + kp0 + tig + 4];
                a_hi[mi][3] = Hh[(rm + g + 8) * HST + kp0 + tig + 4];
            }
            const int kb = ks * 8;
            #pragma unroll
            for (int ni = 0; ni < 4; ni++) {
                int cn = wn * 32 + ni * 8;
                uint32_t b[2];
                b[0] = B[(kb + tig    ) * BST + cn + g];
                b[1] = B[(kb + tig + 4) * BST + cn + g];
                #pragma unroll
                for (int mi = 0; mi < 2; mi++)
                    mma_f16(acc[mi][ni], a_hi[mi], b);
            }
        }
    }

    // ---- epilogue2: bias + ReLU -> packed fp16 OUT ----
    float bb[4][2];
    #pragma unroll
    for (int ni = 0; ni < 4; ni++) {
        #pragma unroll
        for (int j = 0; j < 2; j++)
            bb[ni][j] = b2[wn * 32 + ni * 8 + 2 * tig + j];
    }
    #pragma unroll
    for (int mi = 0; mi < 2; mi++) {
        int r0 = row0 + wm * 32 + mi * 16 + g;
        int r1 = r0 + 8;
        #pragma unroll
        for (int ni = 0; ni < 4; ni++) {
            int c0 = wn * 32 + ni * 8 + 2 * tig;   // even
            int kp = c0 >> 1;
            if (r0 < N_NODES) {
                __half2 o = __floats2half2_rn(
                    fmaxf(acc[mi][ni][0] + bb[ni][0], 0.0f),
                    fmaxf(acc[mi][ni][1] + bb[ni][1], 0.0f));
                OUT16[r0 * KPAIRS + kp] = *(uint32_t*)&o;
            }
            if (r1 < N_NODES) {
                __half2 o = __floats2half2_rn(
                    fmaxf(acc[mi][ni][2] + bb[ni][0], 0.0f),
                    fmaxf(acc[mi][ni][3] + bb[ni][1], 0.0f));
                OUT16[r1 * KPAIRS + kp] = *(uint32_t*)&o;
            }
        }
    }
}

// ---------------- fused pool (segment sum) + MLP head ------------------------
__global__ void pool_head_kernel(const uint32_t* __restrict__ h,
                                 const float* __restrict__ l1w, const float* __restrict__ l1b,
                                 const float* __restrict__ l2w, const float* __restrict__ l2b,
                                 float* __restrict__ out) {
    __shared__ float hg[DIMH];
    __shared__ float o1[LIN1_DIM];
    int gph = blockIdx.x;
    int t = threadIdx.x;       // 0..127 -> feature t
    int u = t >> 1, hi = t & 1;
    int s = g_gstart[gph], e = g_gstart[gph + 1];
    float a0 = 0.f, a1 = 0.f;
    int r = s;
    for (; r + 2 <= e; r += 2) {
        uint32_t v0 = h[r * KPAIRS + u];
        uint32_t v1 = h[(r + 1) * KPAIRS + u];
        float2 f0 = __half22float2(*(__half2*)&v0);
        float2 f1 = __half22float2(*(__half2*)&v1);
        a0 += hi ? f0.y : f0.x;
        a1 += hi ? f1.y : f1.x;
    }
    if (r < e) {
        uint32_t v = h[r * KPAIRS + u];
        float2 f = __half22float2(*(__half2*)&v);
        a0 += hi ? f.y : f.x;
    }
    hg[t] = a0 + a1;
    __syncthreads();
    if (t < LIN1_DIM) {
        float s2 = l1b[t];
        #pragma unroll 8
        for (int k = 0; k < DIMH; k++) s2 += hg[k] * l1w[k * LIN1_DIM + t];
        o1[t] = fmaxf(s2, 0.0f);
    }
    __syncthreads();
    if (t == 0) {
        float s2 = l2b[0];
        #pragma unroll 8
        for (int j = 0; j < LIN1_DIM; j++) s2 += o1[j] * l2w[j];
        out[gph] = 1.0f / (1.0f + expf(-s2));
    }
}

// ---------------- launch ----------------
extern "C" void kernel_launch(void* const* d_in, const int* in_sizes, int n_in,
                              void* d_out, int out_size) {
    const float* x          = (const float*)d_in[0];
    const int*   edge_index = (const int*)d_in[1];
    const int*   batch      = (const int*)d_in[2];
    const float* w[3][7];
    const float* b2[3];
    for (int l = 0; l < 3; l++) {
        int base = 3 + l * 8;
        w[l][0] = (const float*)d_in[base + 0];
        w[l][1] = (const float*)d_in[base + 1];
        w[l][2] = (const float*)d_in[base + 2];
        w[l][3] = (const float*)d_in[base + 3];
        w[l][4] = (const float*)d_in[base + 4];
        w[l][5] = (const float*)d_in[base + 5];
        w[l][6] = (const float*)d_in[base + 6];
        b2[l]   = (const float*)d_in[base + 7];
    }
    const float* l1w = (const float*)d_in[27];
    const float* l1b = (const float*)d_in[28];
    const float* l2w = (const float*)d_in[29];
    const float* l2b = (const float*)d_in[30];
    float* out = (float*)d_out;

    const int* e_src = edge_index;
    const int* e_dst = edge_index + N_EDGES;

    static uint32_t* p_fh   = nullptr;
    static uint32_t* p_ah   = nullptr;
    static uint32_t* p_wsp  = nullptr;
    static int*      p_cnt  = nullptr;
    static cudaStream_t s_aux = nullptr;
    static cudaEvent_t ev_fork = nullptr, ev_join = nullptr;
    if (!p_fh) {
        cudaGetSymbolAddress((void**)&p_fh,  g_fh);
        cudaGetSymbolAddress((void**)&p_ah,  g_ah);
        cudaGetSymbolAddress((void**)&p_wsp, g_wsp);
        cudaGetSymbolAddress((void**)&p_cnt, g_cnt);
        cudaFuncSetAttribute(layer_gemm_kernel,
                             cudaFuncAttributeMaxDynamicSharedMemorySize,
                             SMEM_U32 * 4);
        cudaStreamCreateWithFlags(&s_aux, cudaStreamNonBlocking);
        cudaEventCreateWithFlags(&ev_fork, cudaEventDisableTiming);
        cudaEventCreateWithFlags(&ev_join, cudaEventDisableTiming);
    }

    // ---- fork: aux stream runs CSR-independent setup ----
    cudaEventRecord(ev_fork, 0);
    cudaStreamWaitEvent(s_aux, ev_fork, 0);
    pad_x_kernel<<<(N_NODES * 64 + 255) / 256, 256, 0, s_aux>>>(x);
    gstart_kernel<<<(N_NODES + 255) / 256, 256, 0, s_aux>>>(batch);
    {
        dim3 grid((KPAIRS * 128 + 255) / 256, 6);
        wsplit_kernel<<<grid, 256, 0, s_aux>>>(w[0][0], w[0][6], w[1][0], w[1][6],
                                               w[2][0], w[2][6], IN_DIM);
    }
    cudaEventRecord(ev_join, s_aux);

    // ---- main stream: CSR build ----
    cudaMemsetAsync(p_cnt, 0, (N_NODES + 64) * sizeof(int));
    count_kernel<<<(N_EDGES + 255) / 256, 256>>>(e_dst);
    scan_onepass_kernel<<<SCAN_NB, 1024>>>();
    scatter_kernel<<<(N_EDGES + 255) / 256, 256>>>(e_src, e_dst);

    // ---- join before layers ----
    cudaStreamWaitEvent(0, ev_join, 0);

    const int GEMM_GRID = (N_NODES + 63) / 64;
    const int AGG_GRID  = (N_NODES * 32 + 255) / 256;
    const size_t SMEM   = SMEM_U32 * 4;

    // ---- 3 GIN layers ----
    for (int l = 0; l < 3; l++) {
        agg_kernel<<<AGG_GRID, 256>>>(p_fh, p_ah);
        layer_gemm_kernel<<<GEMM_GRID, 256, SMEM>>>(
            p_ah,
            p_wsp + (2 * l) * KPAIRS * 128, w[l][1], w[l][2], w[l][3],
            w[l][4], w[l][5],
            p_wsp + (2 * l + 1) * KPAIRS * 128, b2[l],
            p_fh);
    }

    // ---- fused pool + head ----
    pool_head_kernel<<<N_GRAPHS, 128>>>(p_fh, l1w, l1b, l2w, l2b, out);
}